// round 2
// baseline (speedup 1.0000x reference)
#include <cuda_runtime.h>
#include <math.h>

#define NROWS 32768
#define HD    512

// ---------------- scratch (device globals: no allocation allowed) ------------
__device__ int   g_cnt0;                 // count of group==0 rows (left)
__device__ int   g_cnt1;                 // count of group==1 rows (right)
__device__ int   g_idx0[NROWS];          // compacted row indices, group==0
__device__ int   g_idx1[NROWS];          // compacted row indices, group==1
__device__ float g_hL[(size_t)NROWS * HD];   // stage-1 output for left rows (compact order)
__device__ float g_hR[(size_t)NROWS * HD];   // stage-1 output for right rows (compact order)

// ---------------- kernel 0: reset counters ----------------------------------
__global__ void reset_kernel() {
    g_cnt0 = 0;
    g_cnt1 = 0;
}

// ---------------- kernel 1: classify + zero finished rows + mask ------------
__global__ void __launch_bounds__(256) classify_kernel(const int* __restrict__ group,
                                                       float* __restrict__ out,
                                                       int write_mask) {
    int row = blockIdx.x;
    int g = group[row];
    if (threadIdx.x == 0) {
        if (g == 0)      { int p = atomicAdd(&g_cnt0, 1); g_idx0[p] = row; }
        else if (g == 1) { int p = atomicAdd(&g_cnt1, 1); g_idx1[p] = row; }
        if (write_mask)
            out[(size_t)NROWS * HD + row] = (g == 2) ? 1.0f : 0.0f;
    }
    if (g == 2) {
        float2* o = (float2*)(out + (size_t)row * HD);
        #pragma unroll
        for (int i = threadIdx.x; i < HD / 2; i += 256)
            o[i] = make_float2(0.0f, 0.0f);
    }
}

// ---------------- fused gated GEMM ------------------------------------------
// Computes  C[i,n] = tanh(A[i,:]@Wh[:,n] + bh[n]) * sigmoid(A[i,:]@Wg[:,n] + bg[n])
// over the compacted row set (idx list chosen by `left`).
//
// MODE 0: stage 1.  A = concat(node_hidden, node_context, label_embedding)[gr]  (K=1536)
//                   writes h into g_hL (left=1) or g_hR (left=0), compact row order.
// MODE 1: stage 2 left.  A = g_hL (compact, K=512). Writes scattered into d_out.
// MODE 2: stage 2 right. A = concat(g_hR[compact], left_embedding[gr]) (K=1024).
//                   Writes scattered into d_out.
//
// Tile: BM=64, BN=64, BK=16.  256 threads, 16x16 grid of 4x4 microtiles.
// Both Wh and Wg streams share one A tile (halves A smem traffic, fuses gate).

template <int MODE>
__global__ void __launch_bounds__(256) gemm_gate(const float* __restrict__ A0,  // node_hidden   (MODE0)
                                                 const float* __restrict__ A1,  // node_context  (MODE0)
                                                 const float* __restrict__ A2,  // label_emb (M0) / left_emb (M2)
                                                 const float* __restrict__ Wh,
                                                 const float* __restrict__ Wg,
                                                 const float* __restrict__ bh,
                                                 const float* __restrict__ bg,
                                                 float* __restrict__ outp,      // d_out for MODE1/2
                                                 int left) {
    constexpr int KD = (MODE == 0) ? 1536 : (MODE == 1) ? 512 : 1024;
    constexpr int BM = 64, BN = 64, BK = 16;

    const int cnt = left ? g_cnt0 : g_cnt1;
    const int* __restrict__ idx = left ? g_idx0 : g_idx1;

    const int row0 = blockIdx.x * BM;
    if (row0 >= cnt) return;
    const int n0 = blockIdx.y * BN;

    __shared__ float As [BK][BM + 4];
    __shared__ float Bhs[BK][BN];
    __shared__ float Bgs[BK][BN];

    const int tid = threadIdx.x;

    // ---- A-loader mapping: each thread loads one float4 (m = tid/4, k-quad)
    const int lm = tid >> 2;            // 0..63
    const int lkq = (tid & 3) * 4;      // 0,4,8,12
    const int lic = row0 + lm;          // compact row index
    const bool lvalid = (lic < cnt);
    int lgr = 0;                        // global row for gathered sources
    if (lvalid && (MODE == 0 || MODE == 2)) lgr = idx[lic];

    // ---- B-loader mapping: n = tid&63, 4 k-rows per thread
    const int bn = tid & 63;
    const int bk0 = (tid >> 6) * 4;     // 0,4,8,12

    // ---- compute mapping
    const int tn = (tid & 15) * 4;      // output col within tile
    const int tm = (tid >> 4) * 4;      // output row within tile

    float acc_h[4][4];
    float acc_g[4][4];
    #pragma unroll
    for (int i = 0; i < 4; i++)
        #pragma unroll
        for (int j = 0; j < 4; j++) { acc_h[i][j] = 0.0f; acc_g[i][j] = 0.0f; }

    for (int k0 = 0; k0 < KD; k0 += BK) {
        // load A tile (64 x 16) as As[k][m]
        float4 av = make_float4(0.f, 0.f, 0.f, 0.f);
        if (lvalid) {
            const int k = k0 + lkq;
            if (MODE == 0) {
                const float* src = (k < 512) ? A0 : (k < 1024) ? A1 : A2;
                av = *(const float4*)(src + (size_t)lgr * HD + (k & 511));
            } else if (MODE == 1) {
                av = *(const float4*)(g_hL + (size_t)lic * HD + k);
            } else {
                if (k < 512)
                    av = *(const float4*)(g_hR + (size_t)lic * HD + k);
                else
                    av = *(const float4*)(A2 + (size_t)lgr * HD + (k - 512));
            }
        }
        As[lkq + 0][lm] = av.x;
        As[lkq + 1][lm] = av.y;
        As[lkq + 2][lm] = av.z;
        As[lkq + 3][lm] = av.w;

        // load B tiles (16 x 64), coalesced over n
        #pragma unroll
        for (int i = 0; i < 4; i++) {
            const int k = bk0 + i;
            Bhs[k][bn] = Wh[(size_t)(k0 + k) * HD + n0 + bn];
            Bgs[k][bn] = Wg[(size_t)(k0 + k) * HD + n0 + bn];
        }
        __syncthreads();

        #pragma unroll
        for (int kk = 0; kk < BK; kk++) {
            float4 a4  = *(const float4*)&As [kk][tm];
            float4 bh4 = *(const float4*)&Bhs[kk][tn];
            float4 bg4 = *(const float4*)&Bgs[kk][tn];
            float a[4]  = {a4.x, a4.y, a4.z, a4.w};
            float bhv[4] = {bh4.x, bh4.y, bh4.z, bh4.w};
            float bgv[4] = {bg4.x, bg4.y, bg4.z, bg4.w};
            #pragma unroll
            for (int i = 0; i < 4; i++)
                #pragma unroll
                for (int j = 0; j < 4; j++) {
                    acc_h[i][j] = fmaf(a[i], bhv[j], acc_h[i][j]);
                    acc_g[i][j] = fmaf(a[i], bgv[j], acc_g[i][j]);
                }
        }
        __syncthreads();
    }

    // ---- epilogue: bias + tanh*sigmoid, write out
    float bhb[4], bgb[4];
    #pragma unroll
    for (int j = 0; j < 4; j++) {
        bhb[j] = bh[n0 + tn + j];
        bgb[j] = bg[n0 + tn + j];
    }

    float* dstbase;
    if (MODE == 0) dstbase = left ? g_hL : g_hR;
    else           dstbase = outp;

    #pragma unroll
    for (int i = 0; i < 4; i++) {
        const int ic = row0 + tm + i;
        if (ic >= cnt) break;
        size_t orow;
        if (MODE == 0) orow = (size_t)ic;          // compact order
        else           orow = (size_t)idx[ic];     // scatter to original row
        float4 v;
        float* vp = (float*)&v;
        #pragma unroll
        for (int j = 0; j < 4; j++) {
            const float th = tanhf(acc_h[i][j] + bhb[j]);
            const float zg = acc_g[i][j] + bgb[j];
            const float sg = 1.0f / (1.0f + expf(-zg));
            vp[j] = th * sg;
        }
        *(float4*)(dstbase + orow * HD + n0 + tn) = v;
    }
}

// ---------------- launch ------------------------------------------------------
extern "C" void kernel_launch(void* const* d_in, const int* in_sizes, int n_in,
                              void* d_out, int out_size) {
    const float* nh   = (const float*)d_in[0];
    const float* nc   = (const float*)d_in[1];
    const float* le   = (const float*)d_in[2];   // label_embedding
    const float* lft  = (const float*)d_in[3];   // left_embedding
    const int*   grp  = (const int*)  d_in[4];
    const float* Wl1h = (const float*)d_in[5];
    const float* bl1h = (const float*)d_in[6];
    const float* Wl1g = (const float*)d_in[7];
    const float* bl1g = (const float*)d_in[8];
    const float* Wl2h = (const float*)d_in[9];
    const float* bl2h = (const float*)d_in[10];
    const float* Wl2g = (const float*)d_in[11];
    const float* bl2g = (const float*)d_in[12];
    const float* Wr1h = (const float*)d_in[13];
    const float* br1h = (const float*)d_in[14];
    const float* Wr1g = (const float*)d_in[15];
    const float* br1g = (const float*)d_in[16];
    const float* Wr2h = (const float*)d_in[17];
    const float* br2h = (const float*)d_in[18];
    const float* Wr2g = (const float*)d_in[19];
    const float* br2g = (const float*)d_in[20];

    float* out = (float*)d_out;
    const int write_mask = (out_size >= NROWS * HD + NROWS) ? 1 : 0;

    reset_kernel<<<1, 1>>>();
    classify_kernel<<<NROWS, 256>>>(grp, out, write_mask);

    dim3 grid(NROWS / 64, HD / 64);

    // stage 1: left rows -> g_hL, right rows -> g_hR
    gemm_gate<0><<<grid, 256>>>(nh, nc, le, Wl1h, Wl1g, bl1h, bl1g, nullptr, 1);
    gemm_gate<0><<<grid, 256>>>(nh, nc, le, Wr1h, Wr1g, br1h, br1g, nullptr, 0);

    // stage 2: left -> out rows idx0 ; right (concat h_r, left_embedding) -> out rows idx1
    gemm_gate<1><<<grid, 256>>>(nullptr, nullptr, nullptr, Wl2h, Wl2g, bl2h, bl2g, out, 1);
    gemm_gate<2><<<grid, 256>>>(nullptr, nullptr, lft,     Wr2h, Wr2g, br2h, br2g, out, 0);
}

// round 6
// speedup vs baseline: 3.3618x; 3.3618x over previous
#include <cuda_runtime.h>
#include <cuda_fp16.h>
#include <math.h>
#include <stdint.h>

#define NROWS 32768
#define HD    512

// ---------------------------------------------------------------------------
// warp-level tensor-core primitives (sm_80+ path; no 'a'-suffix features)
// ---------------------------------------------------------------------------
__device__ __forceinline__ uint32_t smem_to_u32(const void* p) {
    uint32_t a;
    asm("{ .reg .u64 t; cvta.to.shared.u64 t, %1; cvt.u32.u64 %0, t; }" : "=r"(a) : "l"(p));
    return a;
}

#define LDMATRIX_X4(r0, r1, r2, r3, addr) \
    asm volatile("ldmatrix.sync.aligned.m8n8.x4.shared.b16 {%0,%1,%2,%3}, [%4];" \
                 : "=r"(r0), "=r"(r1), "=r"(r2), "=r"(r3) : "r"(addr))
#define LDMATRIX_X2(r0, r1, addr) \
    asm volatile("ldmatrix.sync.aligned.m8n8.x2.shared.b16 {%0,%1}, [%2];" \
                 : "=r"(r0), "=r"(r1) : "r"(addr))
#define MMA16816(c, a, b) \
    asm volatile("mma.sync.aligned.m16n8k16.row.col.f32.f16.f16.f32 " \
                 "{%0,%1,%2,%3}, {%4,%5,%6,%7}, {%8,%9}, {%0,%1,%2,%3};" \
                 : "+f"((c)[0]), "+f"((c)[1]), "+f"((c)[2]), "+f"((c)[3]) \
                 : "r"((a)[0]), "r"((a)[1]), "r"((a)[2]), "r"((a)[3]), \
                   "r"((b)[0]), "r"((b)[1]))

// ---------------------------------------------------------------------------
// device scratch (no allocations allowed)
// ---------------------------------------------------------------------------
__device__ int g_cnt0, g_cnt1;
__device__ int g_idx0[NROWS], g_idx1[NROWS];
__device__ __align__(16) __half g_hL[(size_t)NROWS * HD];   // stage-1 left h (compact)
__device__ __align__(16) __half g_hR[(size_t)NROWS * HD];   // stage-1 right h (compact)
__device__ __align__(16) __half g_W1t[4][512 * 1536];       // l1h,l1g,r1h,r1g  [N][K] fp16
__device__ __align__(16) __half g_W2Lt[2][512 * 512];       // l2h,l2g
__device__ __align__(16) __half g_W2Rt[2][512 * 1024];      // r2h,r2g

// ---------------------------------------------------------------------------
__global__ void reset_kernel() { g_cnt0 = 0; g_cnt1 = 0; }

__global__ void __launch_bounds__(256) classify_kernel(const int* __restrict__ group,
                                                       float* __restrict__ out,
                                                       int write_mask) {
    int row = blockIdx.x;
    int g = group[row];
    if (threadIdx.x == 0) {
        if (g == 0)      { int p = atomicAdd(&g_cnt0, 1); g_idx0[p] = row; }
        else if (g == 1) { int p = atomicAdd(&g_cnt1, 1); g_idx1[p] = row; }
        if (write_mask)
            out[(size_t)NROWS * HD + row] = (g == 2) ? 1.0f : 0.0f;
    }
    if (g == 2) {
        float2* o = (float2*)(out + (size_t)row * HD);
        for (int i = threadIdx.x; i < HD / 2; i += 256)
            o[i] = make_float2(0.0f, 0.0f);
    }
}

// transpose + convert: W [K][512] fp32 -> Wt [512][K] fp16
__global__ void __launch_bounds__(256) wtrans_kernel(const float* __restrict__ W, int K, int id) {
    __shared__ float t[32][33];
    __half* Wt;
    switch (id) {
        case 0: Wt = g_W1t[0];  break;
        case 1: Wt = g_W1t[1];  break;
        case 2: Wt = g_W1t[2];  break;
        case 3: Wt = g_W1t[3];  break;
        case 4: Wt = g_W2Lt[0]; break;
        case 5: Wt = g_W2Lt[1]; break;
        case 6: Wt = g_W2Rt[0]; break;
        default: Wt = g_W2Rt[1]; break;
    }
    int n0 = blockIdx.x * 32, k0 = blockIdx.y * 32;
    int tx = threadIdx.x & 31, ty = threadIdx.x >> 5;
    #pragma unroll
    for (int i = 0; i < 32; i += 8)
        t[ty + i][tx] = W[(size_t)(k0 + ty + i) * 512 + n0 + tx];
    __syncthreads();
    #pragma unroll
    for (int i = 0; i < 32; i += 8)
        Wt[(size_t)(n0 + ty + i) * K + k0 + tx] = __float2half(t[tx][ty + i]);
}

// ---------------------------------------------------------------------------
__device__ __forceinline__ uint4 cvt8(const float4* sp) {
    float4 f0 = sp[0], f1 = sp[1];
    __half2 h0 = __floats2half2_rn(f0.x, f0.y);
    __half2 h1 = __floats2half2_rn(f0.z, f0.w);
    __half2 h2 = __floats2half2_rn(f1.x, f1.y);
    __half2 h3 = __floats2half2_rn(f1.z, f1.w);
    uint4 v;
    v.x = *(uint32_t*)&h0; v.y = *(uint32_t*)&h1;
    v.z = *(uint32_t*)&h2; v.w = *(uint32_t*)&h3;
    return v;
}

// ---------------------------------------------------------------------------
// gated GEMM via mma.sync:  C = tanh(A@Wh + bh) * sigmoid(A@Wg + bg)
// STAGE 1: A = concat(nh, nc, le)[idx] (K=1536), fp16 out -> g_hL/g_hR compact.
// STAGE 2: left A = g_hL (K=512); right A = concat(g_hR, lft[idx]) (K=1024);
//          fp32 out scattered to d_out.
// Tile: BM=128, BN=64 per stream (h+g), BK=32, double-buffered smem.
// 8 warps: (wm 0..3, wn 0..1), each 32(m) x 32(n) x 2 streams.
// ---------------------------------------------------------------------------
#define LDK 40   // padded row stride in halfs (80B: 16B-aligned, conflict-free)

template <int STAGE>
__global__ void __launch_bounds__(256, 2) gemm_mma(
    const float* __restrict__ nh, const float* __restrict__ ncx, const float* __restrict__ le,
    const float* __restrict__ lft,
    const float* __restrict__ bhL, const float* __restrict__ bgL,
    const float* __restrict__ bhR, const float* __restrict__ bgR,
    float* __restrict__ outp)
{
    __shared__ __half sA [2 * 128 * LDK];
    __shared__ __half sBh[2 * 64 * LDK];
    __shared__ __half sBg[2 * 64 * LDK];
    __shared__ int s_idx[128];

    const int tid  = threadIdx.x;
    const int lane = tid & 31;
    const int wid  = tid >> 5;
    const int side = blockIdx.z;

    const int cnt  = side ? g_cnt1 : g_cnt0;
    const int row0 = blockIdx.y * 128;
    if (row0 >= cnt) return;
    const int n0 = blockIdx.x * 64;

    const int* __restrict__ idx = side ? g_idx1 : g_idx0;
    const int K = (STAGE == 1) ? 1536 : (side ? 1024 : 512);
    const __half* __restrict__ Wh;
    const __half* __restrict__ Wg;
    if (STAGE == 1) { Wh = g_W1t[side * 2]; Wg = g_W1t[side * 2 + 1]; }
    else if (side)  { Wh = g_W2Rt[0];       Wg = g_W2Rt[1]; }
    else            { Wh = g_W2Lt[0];       Wg = g_W2Lt[1]; }
    const float* __restrict__ bh = side ? bhR : bhL;
    const float* __restrict__ bg = side ? bgR : bgL;
    const __half* __restrict__ Asrc = side ? g_hR : g_hL;
    __half* __restrict__ hdst       = side ? g_hR : g_hL;

    if (tid < 128) {
        int rc = row0 + tid;
        s_idx[tid] = (rc < cnt) ? idx[rc] : 0;
    }
    __syncthreads();

    // ---- fetch helpers -----------------------------------------------------
    auto fetchA = [&](int t, int kbase) -> uint4 {
        int r = t >> 2, q = t & 3;
        int kk = kbase + q * 8;
        uint4 v = make_uint4(0, 0, 0, 0);
        int rc = row0 + r;
        if (rc < cnt) {
            if (STAGE == 1) {
                int gr = s_idx[r];
                const float* src = (kk < 512) ? nh : (kk < 1024) ? ncx : le;
                v = cvt8((const float4*)(src + (size_t)gr * 512 + (kk & 511)));
            } else if (!side || kk < 512) {
                v = *(const uint4*)(Asrc + (size_t)rc * 512 + kk);
            } else {
                int gr = s_idx[r];
                v = cvt8((const float4*)(lft + (size_t)gr * 512 + (kk - 512)));
            }
        }
        return v;
    };
    const int br = tid >> 2;          // B row (n) 0..63
    const int bq = tid & 3;
    auto fetchB = [&](const __half* W, int kbase) -> uint4 {
        return *(const uint4*)(W + (size_t)(n0 + br) * K + kbase + bq * 8);
    };
    auto storeA = [&](int buf, int t, uint4 v) {
        int r = t >> 2, q = t & 3;
        *(uint4*)&sA[buf * (128 * LDK) + r * LDK + q * 8] = v;
    };
    auto storeBh = [&](int buf, uint4 v) {
        *(uint4*)&sBh[buf * (64 * LDK) + br * LDK + bq * 8] = v;
    };
    auto storeBg = [&](int buf, uint4 v) {
        *(uint4*)&sBg[buf * (64 * LDK) + br * LDK + bq * 8] = v;
    };

    // ---- ldmatrix lane addressing ------------------------------------------
    const int wm = wid & 3;           // m warp 0..3  (32 rows each)
    const int wn = wid >> 2;          // n warp 0..1  (32 cols each)
    const uint32_t sAu  = smem_to_u32(sA);
    const uint32_t sBhu = smem_to_u32(sBh);
    const uint32_t sBgu = smem_to_u32(sBg);
    const int rowA = wm * 32 + (lane & 15);
    const int colA = (lane >> 4) * 8;
    const int rowB = wn * 32 + (lane & 7);
    const int colB = ((lane >> 3) & 1) * 8;

    float ah[2][4][4];
    float ag[2][4][4];
    #pragma unroll
    for (int i = 0; i < 2; i++)
        #pragma unroll
        for (int j = 0; j < 4; j++)
            #pragma unroll
            for (int q = 0; q < 4; q++) { ah[i][j][q] = 0.f; ag[i][j][q] = 0.f; }

    // ---- prologue: chunk 0 -> buf 0 ----------------------------------------
    storeA(0, tid,       fetchA(tid, 0));
    storeA(0, tid + 256, fetchA(tid + 256, 0));
    storeBh(0, fetchB(Wh, 0));
    storeBg(0, fetchB(Wg, 0));
    __syncthreads();

    const int nchunks = K / 32;
    for (int c = 0; c < nchunks; ++c) {
        const int cur = c & 1, nxt = cur ^ 1;
        const bool pf = (c + 1 < nchunks);
        uint4 pa0, pa1, pbh, pbg;
        if (pf) {
            const int kb = (c + 1) * 32;
            pa0 = fetchA(tid, kb);
            pa1 = fetchA(tid + 256, kb);
            pbh = fetchB(Wh, kb);
            pbg = fetchB(Wg, kb);
        }
        // ---- compute on buf cur (2 k16 steps) ----
        #pragma unroll
        for (int k16 = 0; k16 < 2; ++k16) {
            const int kk = k16 * 16;
            uint32_t a[2][4];
            #pragma unroll
            for (int mt = 0; mt < 2; ++mt) {
                uint32_t ad = sAu + 2u * (cur * (128 * LDK) + (rowA + mt * 16) * LDK + kk + colA);
                LDMATRIX_X4(a[mt][0], a[mt][1], a[mt][2], a[mt][3], ad);
            }
            uint32_t bhf[4][2], bgf[4][2];
            #pragma unroll
            for (int nt = 0; nt < 4; ++nt) {
                uint32_t off = 2u * (cur * (64 * LDK) + (rowB + nt * 8) * LDK + kk + colB);
                LDMATRIX_X2(bhf[nt][0], bhf[nt][1], sBhu + off);
                LDMATRIX_X2(bgf[nt][0], bgf[nt][1], sBgu + off);
            }
            #pragma unroll
            for (int mt = 0; mt < 2; ++mt)
                #pragma unroll
                for (int nt = 0; nt < 4; ++nt) {
                    MMA16816(ah[mt][nt], a[mt], bhf[nt]);
                    MMA16816(ag[mt][nt], a[mt], bgf[nt]);
                }
        }
        if (pf) {
            storeA(nxt, tid, pa0);
            storeA(nxt, tid + 256, pa1);
            storeBh(nxt, pbh);
            storeBg(nxt, pbg);
        }
        __syncthreads();
    }

    // ---- epilogue: bias + tanh*sigmoid, fragment-layout stores --------------
    const int r0l   = wm * 32 + (lane >> 2);
    const int cbase = wn * 32 + (lane & 3) * 2;

    float bhv[4][2], bgv[4][2];
    #pragma unroll
    for (int nt = 0; nt < 4; ++nt) {
        int ncol = n0 + cbase + nt * 8;
        bhv[nt][0] = bh[ncol];     bhv[nt][1] = bh[ncol + 1];
        bgv[nt][0] = bg[ncol];     bgv[nt][1] = bg[ncol + 1];
    }

    #pragma unroll
    for (int mt = 0; mt < 2; ++mt) {
        #pragma unroll
        for (int hf = 0; hf < 2; ++hf) {
            const int rloc = r0l + mt * 16 + hf * 8;
            const int rc = row0 + rloc;
            if (rc >= cnt) continue;
            const int gr = s_idx[rloc];
            #pragma unroll
            for (int nt = 0; nt < 4; ++nt) {
                const int ncol = n0 + cbase + nt * 8;
                float hv0 = ah[mt][nt][hf * 2 + 0] + bhv[nt][0];
                float hv1 = ah[mt][nt][hf * 2 + 1] + bhv[nt][1];
                float gv0 = ag[mt][nt][hf * 2 + 0] + bgv[nt][0];
                float gv1 = ag[mt][nt][hf * 2 + 1] + bgv[nt][1];
                float o0 = tanhf(hv0) * (1.0f / (1.0f + __expf(-gv0)));
                float o1 = tanhf(hv1) * (1.0f / (1.0f + __expf(-gv1)));
                if (STAGE == 1) {
                    *(__half2*)&hdst[(size_t)rc * 512 + ncol] = __floats2half2_rn(o0, o1);
                } else {
                    *(float2*)&outp[(size_t)gr * 512 + ncol] = make_float2(o0, o1);
                }
            }
        }
    }
}

// ---------------------------------------------------------------------------
extern "C" void kernel_launch(void* const* d_in, const int* in_sizes, int n_in,
                              void* d_out, int out_size) {
    const float* nh   = (const float*)d_in[0];
    const float* nc   = (const float*)d_in[1];
    const float* le   = (const float*)d_in[2];
    const float* lft  = (const float*)d_in[3];
    const int*   grp  = (const int*)  d_in[4];
    const float* Wl1h = (const float*)d_in[5];
    const float* bl1h = (const float*)d_in[6];
    const float* Wl1g = (const float*)d_in[7];
    const float* bl1g = (const float*)d_in[8];
    const float* Wl2h = (const float*)d_in[9];
    const float* bl2h = (const float*)d_in[10];
    const float* Wl2g = (const float*)d_in[11];
    const float* bl2g = (const float*)d_in[12];
    const float* Wr1h = (const float*)d_in[13];
    const float* br1h = (const float*)d_in[14];
    const float* Wr1g = (const float*)d_in[15];
    const float* br1g = (const float*)d_in[16];
    const float* Wr2h = (const float*)d_in[17];
    const float* br2h = (const float*)d_in[18];
    const float* Wr2g = (const float*)d_in[19];
    const float* br2g = (const float*)d_in[20];

    float* out = (float*)d_out;
    const int write_mask = (out_size >= NROWS * HD + NROWS) ? 1 : 0;

    reset_kernel<<<1, 1>>>();
    classify_kernel<<<NROWS, 256>>>(grp, out, write_mask);

    wtrans_kernel<<<dim3(16, 48), 256>>>(Wl1h, 1536, 0);
    wtrans_kernel<<<dim3(16, 48), 256>>>(Wl1g, 1536, 1);
    wtrans_kernel<<<dim3(16, 48), 256>>>(Wr1h, 1536, 2);
    wtrans_kernel<<<dim3(16, 48), 256>>>(Wr1g, 1536, 3);
    wtrans_kernel<<<dim3(16, 16), 256>>>(Wl2h, 512, 4);
    wtrans_kernel<<<dim3(16, 16), 256>>>(Wl2g, 512, 5);
    wtrans_kernel<<<dim3(16, 32), 256>>>(Wr2h, 1024, 6);
    wtrans_kernel<<<dim3(16, 32), 256>>>(Wr2g, 1024, 7);

    // grid: x = n-tiles (fastest -> A-tile L2 reuse), y = row tiles, z = side
    dim3 grid(8, NROWS / 128, 2);
    gemm_mma<1><<<grid, 256>>>(nh, nc, le, lft, bl1h, bl1g, br1h, br1g, nullptr);
    gemm_mma<2><<<grid, 256>>>(nh, nc, le, lft, bl2h, bl2g, br2h, br2g, out);
}

// round 7
// speedup vs baseline: 4.9746x; 1.4797x over previous
#include <cuda_runtime.h>
#include <cuda_fp16.h>
#include <math.h>
#include <stdint.h>

#define NROWS 32768
#define HD    512

// ---------------------------------------------------------------------------
// primitives (sm_80+ path; no 'a'-suffix features)
// ---------------------------------------------------------------------------
__device__ __forceinline__ uint32_t smem_to_u32(const void* p) {
    uint32_t a;
    asm("{ .reg .u64 t; cvta.to.shared.u64 t, %1; cvt.u32.u64 %0, t; }" : "=r"(a) : "l"(p));
    return a;
}
__device__ __forceinline__ float tanh_ap(float x) {
    float y;
    asm("tanh.approx.f32 %0, %1;" : "=f"(y) : "f"(x));
    return y;
}

#define LDMATRIX_X4(r0, r1, r2, r3, addr) \
    asm volatile("ldmatrix.sync.aligned.m8n8.x4.shared.b16 {%0,%1,%2,%3}, [%4];" \
                 : "=r"(r0), "=r"(r1), "=r"(r2), "=r"(r3) : "r"(addr))
#define LDMATRIX_X2(r0, r1, addr) \
    asm volatile("ldmatrix.sync.aligned.m8n8.x2.shared.b16 {%0,%1}, [%2];" \
                 : "=r"(r0), "=r"(r1) : "r"(addr))
#define MMA16816(c, a, b) \
    asm volatile("mma.sync.aligned.m16n8k16.row.col.f32.f16.f16.f32 " \
                 "{%0,%1,%2,%3}, {%4,%5,%6,%7}, {%8,%9}, {%0,%1,%2,%3};" \
                 : "+f"((c)[0]), "+f"((c)[1]), "+f"((c)[2]), "+f"((c)[3]) \
                 : "r"((a)[0]), "r"((a)[1]), "r"((a)[2]), "r"((a)[3]), \
                   "r"((b)[0]), "r"((b)[1]))
#define CP_ASYNC16(dst, src) \
    asm volatile("cp.async.cg.shared.global [%0], [%1], 16;" :: "r"(dst), "l"(src))
#define CP_COMMIT() asm volatile("cp.async.commit_group;" ::: "memory")
#define CP_WAIT2()  asm volatile("cp.async.wait_group 2;" ::: "memory")

// ---------------------------------------------------------------------------
// device scratch (no allocations allowed)
// ---------------------------------------------------------------------------
__device__ int g_cnt0, g_cnt1;
__device__ int g_idx0[NROWS], g_idx1[NROWS];
__device__ __align__(16) __half g_A1L[(size_t)NROWS * 1536];  // stage-1 A, left (compact fp16)
__device__ __align__(16) __half g_A1R[(size_t)NROWS * 1536];  // stage-1 A, right
__device__ __align__(16) __half g_A2L[(size_t)NROWS * 512];   // stage-2 A, left (= hL)
__device__ __align__(16) __half g_A2R[(size_t)NROWS * 1024];  // stage-2 A, right (= [hR|lft])
__device__ __align__(16) __half g_W1t[4][512 * 1536];         // l1h,l1g,r1h,r1g  [N][K] fp16
__device__ __align__(16) __half g_W2Lt[2][512 * 512];         // l2h,l2g
__device__ __align__(16) __half g_W2Rt[2][512 * 1024];        // r2h,r2g

// ---------------------------------------------------------------------------
__global__ void reset_kernel() { g_cnt0 = 0; g_cnt1 = 0; }

__global__ void __launch_bounds__(256) classify_kernel(const int* __restrict__ group,
                                                       float* __restrict__ out,
                                                       int write_mask) {
    int row = blockIdx.x;
    int g = group[row];
    if (threadIdx.x == 0) {
        if (g == 0)      { int p = atomicAdd(&g_cnt0, 1); g_idx0[p] = row; }
        else if (g == 1) { int p = atomicAdd(&g_cnt1, 1); g_idx1[p] = row; }
        if (write_mask)
            out[(size_t)NROWS * HD + row] = (g == 2) ? 1.0f : 0.0f;
    }
    if (g == 2) {
        float2* o = (float2*)(out + (size_t)row * HD);
        for (int i = threadIdx.x; i < HD / 2; i += 256)
            o[i] = make_float2(0.0f, 0.0f);
    }
}

__device__ __forceinline__ uint4 cvt8(const float4* sp) {
    float4 f0 = sp[0], f1 = sp[1];
    __half2 h0 = __floats2half2_rn(f0.x, f0.y);
    __half2 h1 = __floats2half2_rn(f0.z, f0.w);
    __half2 h2 = __floats2half2_rn(f1.x, f1.y);
    __half2 h3 = __floats2half2_rn(f1.z, f1.w);
    uint4 v;
    v.x = *(uint32_t*)&h0; v.y = *(uint32_t*)&h1;
    v.z = *(uint32_t*)&h2; v.w = *(uint32_t*)&h3;
    return v;
}

// gather + convert compact A buffers
__global__ void __launch_bounds__(256) gather_kernel(const float* __restrict__ nh,
                                                     const float* __restrict__ ncx,
                                                     const float* __restrict__ le,
                                                     const float* __restrict__ lft) {
    const int side = blockIdx.y;
    const int i = blockIdx.x;
    const int cnt = side ? g_cnt1 : g_cnt0;
    if (i >= cnt) return;
    const int gr = (side ? g_idx1 : g_idx0)[i];
    __half* dst1 = (side ? g_A1R : g_A1L) + (size_t)i * 1536;
    const int t = threadIdx.x;
    if (t < 192) {
        int kk = t * 8;
        const float* src = (kk < 512) ? nh : (kk < 1024) ? ncx : le;
        *(uint4*)(dst1 + kk) = cvt8((const float4*)(src + (size_t)gr * 512 + (kk & 511)));
    } else if (side) {
        int kk = (t - 192) * 8;  // 64 threads x 8 halfs = 512
        *(uint4*)(g_A2R + (size_t)i * 1024 + 512 + kk) =
            cvt8((const float4*)(lft + (size_t)gr * 512 + kk));
    }
}

// merged transpose+convert: 8 weights in one launch. id = blockIdx.z
__global__ void __launch_bounds__(256) wtrans_all(
    const float* __restrict__ W0, const float* __restrict__ W1,
    const float* __restrict__ W2, const float* __restrict__ W3,
    const float* __restrict__ W4, const float* __restrict__ W5,
    const float* __restrict__ W6, const float* __restrict__ W7)
{
    __shared__ float t[32][33];
    const int id = blockIdx.z;
    const int K = (id < 4) ? 1536 : (id < 6) ? 512 : 1024;
    const int k0 = blockIdx.y * 32;
    if (k0 >= K) return;
    const float* W;
    __half* Wt;
    switch (id) {
        case 0: W = W0; Wt = g_W1t[0];  break;
        case 1: W = W1; Wt = g_W1t[1];  break;
        case 2: W = W2; Wt = g_W1t[2];  break;
        case 3: W = W3; Wt = g_W1t[3];  break;
        case 4: W = W4; Wt = g_W2Lt[0]; break;
        case 5: W = W5; Wt = g_W2Lt[1]; break;
        case 6: W = W6; Wt = g_W2Rt[0]; break;
        default: W = W7; Wt = g_W2Rt[1]; break;
    }
    const int n0 = blockIdx.x * 32;
    const int tx = threadIdx.x & 31, ty = threadIdx.x >> 5;
    #pragma unroll
    for (int i = 0; i < 32; i += 8)
        t[ty + i][tx] = W[(size_t)(k0 + ty + i) * 512 + n0 + tx];
    __syncthreads();
    #pragma unroll
    for (int i = 0; i < 32; i += 8)
        Wt[(size_t)(n0 + ty + i) * K + k0 + tx] = __float2half(t[tx][ty + i]);
}

// ---------------------------------------------------------------------------
// gated GEMM, cp.async 4-stage pipeline:
//   C = tanh(A@Wh + bh) * sigmoid(A@Wg + bg)
// STAGE 1: A = g_A1{L,R} (K=1536), fp16 out -> g_A2L / g_A2R[:,0:512] compact.
// STAGE 2: A = g_A2L (K=512) / g_A2R (K=1024); fp32 out scattered to d_out.
// BM=128, BN=64 per stream (h+g), BK=32. 8 warps, each 32m x 32n x 2 streams.
// ---------------------------------------------------------------------------
#define NST   4
#define BK    32
#define LDK   40                    // padded row stride in halfs (80B)
#define ST_A  (128 * LDK)           // 5120 halfs
#define ST_B  (64 * LDK)            // 2560 halfs
#define ST_TOT (ST_A + 2 * ST_B)    // 10240 halfs = 20480 B per stage
#define SMEM_BYTES (NST * ST_TOT * 2)   // 81920 B

template <int STAGE>
__global__ void __launch_bounds__(256, 2) gemm_cp(
    const float* __restrict__ bhL, const float* __restrict__ bgL,
    const float* __restrict__ bhR, const float* __restrict__ bgR,
    float* __restrict__ outp)
{
    extern __shared__ __half smem[];
    __shared__ int s_idx[128];

    const int tid  = threadIdx.x;
    const int lane = tid & 31;
    const int wid  = tid >> 5;
    const int side = blockIdx.z;

    const int cnt  = side ? g_cnt1 : g_cnt0;
    const int row0 = blockIdx.y * 128;
    if (row0 >= cnt) return;
    const int n0 = blockIdx.x * 64;

    const int K = (STAGE == 1) ? 1536 : (side ? 1024 : 512);
    const __half* __restrict__ A;
    const __half* __restrict__ Wh;
    const __half* __restrict__ Wg;
    if (STAGE == 1) {
        A  = side ? g_A1R : g_A1L;
        Wh = g_W1t[side * 2];
        Wg = g_W1t[side * 2 + 1];
    } else {
        A  = side ? g_A2R : g_A2L;
        Wh = side ? g_W2Rt[0] : g_W2Lt[0];
        Wg = side ? g_W2Rt[1] : g_W2Lt[1];
    }
    const float* __restrict__ bh = side ? bhR : bhL;
    const float* __restrict__ bg = side ? bgR : bgL;
    __half* __restrict__ hdst = side ? g_A2R : g_A2L;
    const int K2dst = side ? 1024 : 512;   // stage-1 output row stride

    if (STAGE == 2 && tid < 128) {
        int rc = row0 + tid;
        s_idx[tid] = (rc < cnt) ? (side ? g_idx1 : g_idx0)[rc] : 0;
    }

    const uint32_t sb = smem_to_u32(smem);

    // ---- cp.async issue for chunk c ----------------------------------------
    auto issue = [&](int c) {
        const int buf = c & (NST - 1);
        const uint32_t base = buf * ST_TOT;
        const int kb = c * BK;
        // A: 128 rows x 32 halfs = 512 x 16B lines; 2 per thread
        #pragma unroll
        for (int it = 0; it < 2; ++it) {
            int l = tid + it * 256;
            int r = l >> 2, q = l & 3;
            uint32_t dst = sb + 2u * (base + r * LDK + q * 8);
            const __half* src = A + (size_t)(row0 + r) * K + kb + q * 8;
            CP_ASYNC16(dst, src);
        }
        // Bh / Bg: 64 rows x 32 halfs = 256 lines each; 1 per thread
        {
            int r = tid >> 2, q = tid & 3;
            uint32_t dh = sb + 2u * (base + ST_A + r * LDK + q * 8);
            uint32_t dg = sb + 2u * (base + ST_A + ST_B + r * LDK + q * 8);
            CP_ASYNC16(dh, Wh + (size_t)(n0 + r) * K + kb + q * 8);
            CP_ASYNC16(dg, Wg + (size_t)(n0 + r) * K + kb + q * 8);
        }
    };

    // ---- fragment addressing ------------------------------------------------
    const int wm = wid & 3;
    const int wn = wid >> 2;
    const int rowA = wm * 32 + (lane & 15);
    const int colA = (lane >> 4) * 8;
    const int rowB = wn * 32 + (lane & 7);
    const int colB = ((lane >> 3) & 1) * 8;

    float ah[2][4][4];
    float ag[2][4][4];
    #pragma unroll
    for (int i = 0; i < 2; i++)
        #pragma unroll
        for (int j = 0; j < 4; j++)
            #pragma unroll
            for (int q = 0; q < 4; q++) { ah[i][j][q] = 0.f; ag[i][j][q] = 0.f; }

    const int nch = K / BK;
    #pragma unroll
    for (int s = 0; s < NST - 1; ++s) {
        if (s < nch) issue(s);
        CP_COMMIT();
    }

    for (int c = 0; c < nch; ++c) {
        CP_WAIT2();
        __syncthreads();
        const uint32_t base = (uint32_t)(c & (NST - 1)) * ST_TOT;
        #pragma unroll
        for (int k16 = 0; k16 < 2; ++k16) {
            const int kk = k16 * 16;
            uint32_t a[2][4];
            #pragma unroll
            for (int mt = 0; mt < 2; ++mt) {
                uint32_t ad = sb + 2u * (base + (rowA + mt * 16) * LDK + kk + colA);
                LDMATRIX_X4(a[mt][0], a[mt][1], a[mt][2], a[mt][3], ad);
            }
            uint32_t bhf[4][2], bgf[4][2];
            #pragma unroll
            for (int nt = 0; nt < 4; ++nt) {
                uint32_t oh = sb + 2u * (base + ST_A + (rowB + nt * 8) * LDK + kk + colB);
                LDMATRIX_X2(bhf[nt][0], bhf[nt][1], oh);
                LDMATRIX_X2(bgf[nt][0], bgf[nt][1], oh + 2u * ST_B);
            }
            #pragma unroll
            for (int mt = 0; mt < 2; ++mt)
                #pragma unroll
                for (int nt = 0; nt < 4; ++nt) {
                    MMA16816(ah[mt][nt], a[mt], bhf[nt]);
                    MMA16816(ag[mt][nt], a[mt], bgf[nt]);
                }
        }
        const int nc2 = c + NST - 1;
        __syncthreads();
        if (nc2 < nch) issue(nc2);
        CP_COMMIT();
    }

    // ---- epilogue: bias + tanh * sigmoid ------------------------------------
    const int r0l   = wm * 32 + (lane >> 2);
    const int cbase = wn * 32 + (lane & 3) * 2;

    float bhv[4][2], bgv[4][2];
    #pragma unroll
    for (int nt = 0; nt < 4; ++nt) {
        int ncol = n0 + cbase + nt * 8;
        bhv[nt][0] = bh[ncol]; bhv[nt][1] = bh[ncol + 1];
        bgv[nt][0] = bg[ncol]; bgv[nt][1] = bg[ncol + 1];
    }

    #pragma unroll
    for (int mt = 0; mt < 2; ++mt) {
        #pragma unroll
        for (int hf = 0; hf < 2; ++hf) {
            const int rloc = r0l + mt * 16 + hf * 8;
            const int rc = row0 + rloc;
            if (rc >= cnt) continue;
            #pragma unroll
            for (int nt = 0; nt < 4; ++nt) {
                const int ncol = n0 + cbase + nt * 8;
                float hv0 = ah[mt][nt][hf * 2 + 0] + bhv[nt][0];
                float hv1 = ah[mt][nt][hf * 2 + 1] + bhv[nt][1];
                float gv0 = ag[mt][nt][hf * 2 + 0] + bgv[nt][0];
                float gv1 = ag[mt][nt][hf * 2 + 1] + bgv[nt][1];
                float o0 = tanh_ap(hv0) * (0.5f * tanh_ap(0.5f * gv0) + 0.5f);
                float o1 = tanh_ap(hv1) * (0.5f * tanh_ap(0.5f * gv1) + 0.5f);
                if (STAGE == 1) {
                    *(__half2*)&hdst[(size_t)rc * K2dst + ncol] = __floats2half2_rn(o0, o1);
                } else {
                    *(float2*)&outp[(size_t)s_idx[rloc] * 512 + ncol] = make_float2(o0, o1);
                }
            }
        }
    }
}

// ---------------------------------------------------------------------------
extern "C" void kernel_launch(void* const* d_in, const int* in_sizes, int n_in,
                              void* d_out, int out_size) {
    const float* nh   = (const float*)d_in[0];
    const float* nc   = (const float*)d_in[1];
    const float* le   = (const float*)d_in[2];
    const float* lft  = (const float*)d_in[3];
    const int*   grp  = (const int*)  d_in[4];
    const float* Wl1h = (const float*)d_in[5];
    const float* bl1h = (const float*)d_in[6];
    const float* Wl1g = (const float*)d_in[7];
    const float* bl1g = (const float*)d_in[8];
    const float* Wl2h = (const float*)d_in[9];
    const float* bl2h = (const float*)d_in[10];
    const float* Wl2g = (const float*)d_in[11];
    const float* bl2g = (const float*)d_in[12];
    const float* Wr1h = (const float*)d_in[13];
    const float* br1h = (const float*)d_in[14];
    const float* Wr1g = (const float*)d_in[15];
    const float* br1g = (const float*)d_in[16];
    const float* Wr2h = (const float*)d_in[17];
    const float* br2h = (const float*)d_in[18];
    const float* Wr2g = (const float*)d_in[19];
    const float* br2g = (const float*)d_in[20];

    float* out = (float*)d_out;
    const int write_mask = (out_size >= NROWS * HD + NROWS) ? 1 : 0;

    cudaFuncSetAttribute(gemm_cp<1>, cudaFuncAttributeMaxDynamicSharedMemorySize, SMEM_BYTES);
    cudaFuncSetAttribute(gemm_cp<2>, cudaFuncAttributeMaxDynamicSharedMemorySize, SMEM_BYTES);

    reset_kernel<<<1, 1>>>();
    classify_kernel<<<NROWS, 256>>>(grp, out, write_mask);
    gather_kernel<<<dim3(NROWS, 2), 256>>>(nh, nc, le, lft);
    wtrans_all<<<dim3(16, 48, 8), 256>>>(Wl1h, Wl1g, Wr1h, Wr1g, Wl2h, Wl2g, Wr2h, Wr2g);

    dim3 grid(8, NROWS / 128, 2);
    gemm_cp<1><<<grid, 256, SMEM_BYTES>>>(bl1h, bl1g, br1h, br1g, nullptr);
    gemm_cp<2><<<grid, 256, SMEM_BYTES>>>(bl2h, bl2g, br2h, br2g, out);
}

// round 8
// speedup vs baseline: 5.3891x; 1.0833x over previous
#include <cuda_runtime.h>
#include <cuda_fp16.h>
#include <math.h>
#include <stdint.h>

#define NROWS 32768
#define HD    512

// ---------------------------------------------------------------------------
// primitives (sm_80+ path; no 'a'-suffix features)
// ---------------------------------------------------------------------------
__device__ __forceinline__ uint32_t smem_to_u32(const void* p) {
    uint32_t a;
    asm("{ .reg .u64 t; cvta.to.shared.u64 t, %1; cvt.u32.u64 %0, t; }" : "=r"(a) : "l"(p));
    return a;
}
__device__ __forceinline__ float tanh_ap(float x) {
    float y;
    asm("tanh.approx.f32 %0, %1;" : "=f"(y) : "f"(x));
    return y;
}

#define LDMATRIX_X4(r0, r1, r2, r3, addr) \
    asm volatile("ldmatrix.sync.aligned.m8n8.x4.shared.b16 {%0,%1,%2,%3}, [%4];" \
                 : "=r"(r0), "=r"(r1), "=r"(r2), "=r"(r3) : "r"(addr))
#define MMA16816(c, a, b) \
    asm volatile("mma.sync.aligned.m16n8k16.row.col.f32.f16.f16.f32 " \
                 "{%0,%1,%2,%3}, {%4,%5,%6,%7}, {%8,%9}, {%0,%1,%2,%3};" \
                 : "+f"((c)[0]), "+f"((c)[1]), "+f"((c)[2]), "+f"((c)[3]) \
                 : "r"((a)[0]), "r"((a)[1]), "r"((a)[2]), "r"((a)[3]), \
                   "r"((b)[0]), "r"((b)[1]))
#define CP_ASYNC16(dst, src) \
    asm volatile("cp.async.cg.shared.global [%0], [%1], 16;" :: "r"(dst), "l"(src))
#define CP_COMMIT() asm volatile("cp.async.commit_group;" ::: "memory")
#define CP_WAIT2()  asm volatile("cp.async.wait_group 2;" ::: "memory")

// ---------------------------------------------------------------------------
// device scratch (no allocations allowed)
// ---------------------------------------------------------------------------
__device__ int g_cnt0, g_cnt1;
__device__ int g_idx0[NROWS], g_idx1[NROWS];
__device__ __align__(16) __half g_A1L[(size_t)NROWS * 1536];  // stage-1 A, left (compact fp16)
__device__ __align__(16) __half g_A1R[(size_t)NROWS * 1536];  // stage-1 A, right
__device__ __align__(16) __half g_A2L[(size_t)NROWS * 512];   // stage-2 A, left (= hL)
__device__ __align__(16) __half g_A2R[(size_t)NROWS * 1024];  // stage-2 A, right (= [hR|lft])
__device__ __align__(16) __half g_W1t[4][512 * 1536];         // l1h,l1g,r1h,r1g  [N][K] fp16
__device__ __align__(16) __half g_W2Lt[2][512 * 512];         // l2h,l2g
__device__ __align__(16) __half g_W2Rt[2][512 * 1024];        // r2h,r2g

// ---------------------------------------------------------------------------
__global__ void reset_kernel() { g_cnt0 = 0; g_cnt1 = 0; }

__global__ void __launch_bounds__(256) classify_kernel(const int* __restrict__ group,
                                                       float* __restrict__ out,
                                                       int write_mask) {
    int row = blockIdx.x;
    int g = group[row];
    if (threadIdx.x == 0) {
        if (g == 0)      { int p = atomicAdd(&g_cnt0, 1); g_idx0[p] = row; }
        else if (g == 1) { int p = atomicAdd(&g_cnt1, 1); g_idx1[p] = row; }
        if (write_mask)
            out[(size_t)NROWS * HD + row] = (g == 2) ? 1.0f : 0.0f;
    }
    if (g == 2) {
        float2* o = (float2*)(out + (size_t)row * HD);
        for (int i = threadIdx.x; i < HD / 2; i += 256)
            o[i] = make_float2(0.0f, 0.0f);
    }
}

__device__ __forceinline__ uint4 cvt8(const float4* sp) {
    float4 f0 = sp[0], f1 = sp[1];
    __half2 h0 = __floats2half2_rn(f0.x, f0.y);
    __half2 h1 = __floats2half2_rn(f0.z, f0.w);
    __half2 h2 = __floats2half2_rn(f1.x, f1.y);
    __half2 h3 = __floats2half2_rn(f1.z, f1.w);
    uint4 v;
    v.x = *(uint32_t*)&h0; v.y = *(uint32_t*)&h1;
    v.z = *(uint32_t*)&h2; v.w = *(uint32_t*)&h3;
    return v;
}

// gather + convert compact A buffers
__global__ void __launch_bounds__(256) gather_kernel(const float* __restrict__ nh,
                                                     const float* __restrict__ ncx,
                                                     const float* __restrict__ le,
                                                     const float* __restrict__ lft) {
    const int side = blockIdx.y;
    const int i = blockIdx.x;
    const int cnt = side ? g_cnt1 : g_cnt0;
    if (i >= cnt) return;
    const int gr = (side ? g_idx1 : g_idx0)[i];
    __half* dst1 = (side ? g_A1R : g_A1L) + (size_t)i * 1536;
    const int t = threadIdx.x;
    if (t < 192) {
        int kk = t * 8;
        const float* src = (kk < 512) ? nh : (kk < 1024) ? ncx : le;
        *(uint4*)(dst1 + kk) = cvt8((const float4*)(src + (size_t)gr * 512 + (kk & 511)));
    } else if (side) {
        int kk = (t - 192) * 8;  // 64 threads x 8 halfs = 512
        *(uint4*)(g_A2R + (size_t)i * 1024 + 512 + kk) =
            cvt8((const float4*)(lft + (size_t)gr * 512 + kk));
    }
}

// merged transpose+convert: 8 weights in one launch. id = blockIdx.z
__global__ void __launch_bounds__(256) wtrans_all(
    const float* __restrict__ W0, const float* __restrict__ W1,
    const float* __restrict__ W2, const float* __restrict__ W3,
    const float* __restrict__ W4, const float* __restrict__ W5,
    const float* __restrict__ W6, const float* __restrict__ W7)
{
    __shared__ float t[32][33];
    const int id = blockIdx.z;
    const int K = (id < 4) ? 1536 : (id < 6) ? 512 : 1024;
    const int k0 = blockIdx.y * 32;
    if (k0 >= K) return;
    const float* W;
    __half* Wt;
    switch (id) {
        case 0: W = W0; Wt = g_W1t[0];  break;
        case 1: W = W1; Wt = g_W1t[1];  break;
        case 2: W = W2; Wt = g_W1t[2];  break;
        case 3: W = W3; Wt = g_W1t[3];  break;
        case 4: W = W4; Wt = g_W2Lt[0]; break;
        case 5: W = W5; Wt = g_W2Lt[1]; break;
        case 6: W = W6; Wt = g_W2Rt[0]; break;
        default: W = W7; Wt = g_W2Rt[1]; break;
    }
    const int n0 = blockIdx.x * 32;
    const int tx = threadIdx.x & 31, ty = threadIdx.x >> 5;
    #pragma unroll
    for (int i = 0; i < 32; i += 8)
        t[ty + i][tx] = W[(size_t)(k0 + ty + i) * 512 + n0 + tx];
    __syncthreads();
    #pragma unroll
    for (int i = 0; i < 32; i += 8)
        Wt[(size_t)(n0 + ty + i) * K + k0 + tx] = __float2half(t[tx][ty + i]);
}

// ---------------------------------------------------------------------------
// gated GEMM, cp.async 4-stage pipeline, single barrier per chunk:
//   C = tanh(A@Wh + bh) * sigmoid(A@Wg + bg)
// STAGE 1: A = g_A1{L,R} (K=1536), fp16 out -> g_A2L / g_A2R[:,0:512] compact.
// STAGE 2: A = g_A2L (K=512) / g_A2R (K=1024); fp32 out scattered to d_out.
// BM=128, BN=64 per stream (h+g), BK=32. 8 warps, each 32m x 32n x 2 streams.
// ---------------------------------------------------------------------------
#define NST   4
#define BK    32
#define LDK   40                    // padded row stride in halfs (80B)
#define ST_A  (128 * LDK)           // 5120 halfs
#define ST_B  (64 * LDK)            // 2560 halfs
#define ST_TOT (ST_A + 2 * ST_B)    // 10240 halfs = 20480 B per stage
#define SMEM_BYTES (NST * ST_TOT * 2)   // 81920 B

template <int STAGE>
__global__ void __launch_bounds__(256, 2) gemm_cp(
    const float* __restrict__ bhL, const float* __restrict__ bgL,
    const float* __restrict__ bhR, const float* __restrict__ bgR,
    float* __restrict__ outp)
{
    extern __shared__ __half smem[];
    __shared__ int s_idx[128];

    const int tid  = threadIdx.x;
    const int lane = tid & 31;
    const int wid  = tid >> 5;
    const int side = blockIdx.z;

    const int cnt  = side ? g_cnt1 : g_cnt0;
    const int row0 = blockIdx.y * 128;
    if (row0 >= cnt) return;
    const int n0 = blockIdx.x * 64;

    const int K = (STAGE == 1) ? 1536 : (side ? 1024 : 512);
    const __half* __restrict__ A;
    const __half* __restrict__ Wh;
    const __half* __restrict__ Wg;
    if (STAGE == 1) {
        A  = side ? g_A1R : g_A1L;
        Wh = g_W1t[side * 2];
        Wg = g_W1t[side * 2 + 1];
    } else {
        A  = side ? g_A2R : g_A2L;
        Wh = side ? g_W2Rt[0] : g_W2Lt[0];
        Wg = side ? g_W2Rt[1] : g_W2Lt[1];
    }
    const float* __restrict__ bh = side ? bhR : bhL;
    const float* __restrict__ bg = side ? bgR : bgL;
    __half* __restrict__ hdst = side ? g_A2R : g_A2L;
    const int K2dst = side ? 1024 : 512;   // stage-1 output row stride

    if (STAGE == 2 && tid < 128) {
        int rc = row0 + tid;
        s_idx[tid] = (rc < cnt) ? (side ? g_idx1 : g_idx0)[rc] : 0;
    }

    const uint32_t sb = smem_to_u32(smem);

    // ---- cp.async issue for chunk c ----------------------------------------
    auto issue = [&](int c) {
        const int buf = c & (NST - 1);
        const uint32_t base = buf * ST_TOT;
        const int kb = c * BK;
        // A: 128 rows x 32 halfs = 512 x 16B lines; 2 per thread
        #pragma unroll
        for (int it = 0; it < 2; ++it) {
            int l = tid + it * 256;
            int r = l >> 2, q = l & 3;
            uint32_t dst = sb + 2u * (base + r * LDK + q * 8);
            const __half* src = A + (size_t)(row0 + r) * K + kb + q * 8;
            CP_ASYNC16(dst, src);
        }
        // Bh / Bg: 64 rows x 32 halfs = 256 lines each; 1 per thread
        {
            int r = tid >> 2, q = tid & 3;
            uint32_t dh = sb + 2u * (base + ST_A + r * LDK + q * 8);
            uint32_t dg = sb + 2u * (base + ST_A + ST_B + r * LDK + q * 8);
            CP_ASYNC16(dh, Wh + (size_t)(n0 + r) * K + kb + q * 8);
            CP_ASYNC16(dg, Wg + (size_t)(n0 + r) * K + kb + q * 8);
        }
    };

    // ---- fragment addressing ------------------------------------------------
    const int wm = wid & 3;
    const int wn = wid >> 2;
    const int rowA = wm * 32 + (lane & 15);
    const int colA = (lane >> 4) * 8;
    // B via ldmatrix.x4: m0/m1 = rows n..n+7 (k lo/hi), m2/m3 = rows n+8..n+15
    const int rowB = wn * 32 + (lane & 7) + ((lane >> 4) << 3);
    const int colB = ((lane >> 3) & 1) * 8;

    float ah[2][4][4];
    float ag[2][4][4];
    #pragma unroll
    for (int i = 0; i < 2; i++)
        #pragma unroll
        for (int j = 0; j < 4; j++)
            #pragma unroll
            for (int q = 0; q < 4; q++) { ah[i][j][q] = 0.f; ag[i][j][q] = 0.f; }

    const int nch = K / BK;
    #pragma unroll
    for (int s = 0; s < NST - 1; ++s) {
        if (s < nch) issue(s);
        CP_COMMIT();
    }

    for (int c = 0; c < nch; ++c) {
        CP_WAIT2();
        __syncthreads();
        // prefetch chunk c+3 immediately: its buffer ((c-1)&3) was fully
        // consumed before the barrier above.
        const int nc2 = c + NST - 1;
        if (nc2 < nch) issue(nc2);
        CP_COMMIT();

        const uint32_t base = (uint32_t)(c & (NST - 1)) * ST_TOT;
        #pragma unroll
        for (int k16 = 0; k16 < 2; ++k16) {
            const int kk = k16 * 16;
            uint32_t a[2][4];
            #pragma unroll
            for (int mt = 0; mt < 2; ++mt) {
                uint32_t ad = sb + 2u * (base + (rowA + mt * 16) * LDK + kk + colA);
                LDMATRIX_X4(a[mt][0], a[mt][1], a[mt][2], a[mt][3], ad);
            }
            uint32_t bhf[4][2], bgf[4][2];
            #pragma unroll
            for (int p = 0; p < 2; ++p) {
                uint32_t oh = sb + 2u * (base + ST_A + (rowB + p * 16) * LDK + kk + colB);
                LDMATRIX_X4(bhf[2 * p][0], bhf[2 * p][1], bhf[2 * p + 1][0], bhf[2 * p + 1][1], oh);
                LDMATRIX_X4(bgf[2 * p][0], bgf[2 * p][1], bgf[2 * p + 1][0], bgf[2 * p + 1][1],
                            oh + 2u * ST_B);
            }
            #pragma unroll
            for (int mt = 0; mt < 2; ++mt)
                #pragma unroll
                for (int nt = 0; nt < 4; ++nt) {
                    MMA16816(ah[mt][nt], a[mt], bhf[nt]);
                    MMA16816(ag[mt][nt], a[mt], bgf[nt]);
                }
        }
    }

    // ---- epilogue: bias + tanh * sigmoid ------------------------------------
    const int r0l   = wm * 32 + (lane >> 2);
    const int cbase = wn * 32 + (lane & 3) * 2;

    float bhv[4][2], bgv[4][2];
    #pragma unroll
    for (int nt = 0; nt < 4; ++nt) {
        int ncol = n0 + cbase + nt * 8;
        bhv[nt][0] = bh[ncol]; bhv[nt][1] = bh[ncol + 1];
        bgv[nt][0] = bg[ncol]; bgv[nt][1] = bg[ncol + 1];
    }

    #pragma unroll
    for (int mt = 0; mt < 2; ++mt) {
        #pragma unroll
        for (int hf = 0; hf < 2; ++hf) {
            const int rloc = r0l + mt * 16 + hf * 8;
            const int rc = row0 + rloc;
            if (rc >= cnt) continue;
            #pragma unroll
            for (int nt = 0; nt < 4; ++nt) {
                const int ncol = n0 + cbase + nt * 8;
                float hv0 = ah[mt][nt][hf * 2 + 0] + bhv[nt][0];
                float hv1 = ah[mt][nt][hf * 2 + 1] + bhv[nt][1];
                float gv0 = ag[mt][nt][hf * 2 + 0] + bgv[nt][0];
                float gv1 = ag[mt][nt][hf * 2 + 1] + bgv[nt][1];
                float o0 = tanh_ap(hv0) * (0.5f * tanh_ap(0.5f * gv0) + 0.5f);
                float o1 = tanh_ap(hv1) * (0.5f * tanh_ap(0.5f * gv1) + 0.5f);
                if (STAGE == 1) {
                    *(__half2*)&hdst[(size_t)rc * K2dst + ncol] = __floats2half2_rn(o0, o1);
                } else {
                    *(float2*)&outp[(size_t)s_idx[rloc] * 512 + ncol] = make_float2(o0, o1);
                }
            }
        }
    }
}

// ---------------------------------------------------------------------------
extern "C" void kernel_launch(void* const* d_in, const int* in_sizes, int n_in,
                              void* d_out, int out_size) {
    const float* nh   = (const float*)d_in[0];
    const float* nc   = (const float*)d_in[1];
    const float* le   = (const float*)d_in[2];
    const float* lft  = (const float*)d_in[3];
    const int*   grp  = (const int*)  d_in[4];
    const float* Wl1h = (const float*)d_in[5];
    const float* bl1h = (const float*)d_in[6];
    const float* Wl1g = (const float*)d_in[7];
    const float* bl1g = (const float*)d_in[8];
    const float* Wl2h = (const float*)d_in[9];
    const float* bl2h = (const float*)d_in[10];
    const float* Wl2g = (const float*)d_in[11];
    const float* bl2g = (const float*)d_in[12];
    const float* Wr1h = (const float*)d_in[13];
    const float* br1h = (const float*)d_in[14];
    const float* Wr1g = (const float*)d_in[15];
    const float* br1g = (const float*)d_in[16];
    const float* Wr2h = (const float*)d_in[17];
    const float* br2h = (const float*)d_in[18];
    const float* Wr2g = (const float*)d_in[19];
    const float* br2g = (const float*)d_in[20];

    float* out = (float*)d_out;
    const int write_mask = (out_size >= NROWS * HD + NROWS) ? 1 : 0;

    cudaFuncSetAttribute(gemm_cp<1>, cudaFuncAttributeMaxDynamicSharedMemorySize, SMEM_BYTES);
    cudaFuncSetAttribute(gemm_cp<2>, cudaFuncAttributeMaxDynamicSharedMemorySize, SMEM_BYTES);

    reset_kernel<<<1, 1>>>();
    classify_kernel<<<NROWS, 256>>>(grp, out, write_mask);
    gather_kernel<<<dim3(NROWS, 2), 256>>>(nh, nc, le, lft);
    wtrans_all<<<dim3(16, 48, 8), 256>>>(Wl1h, Wl1g, Wr1h, Wr1g, Wl2h, Wl2g, Wr2h, Wr2g);

    dim3 grid(8, NROWS / 128, 2);
    gemm_cp<1><<<grid, 256, SMEM_BYTES>>>(bl1h, bl1g, br1h, br1g, nullptr);
    gemm_cp<2><<<grid, 256, SMEM_BYTES>>>(bl2h, bl2g, br2h, br2g, out);
}

// round 11
// speedup vs baseline: 5.5067x; 1.0218x over previous
#include <cuda_runtime.h>
#include <cuda_fp16.h>
#include <math.h>
#include <stdint.h>

#define NROWS 32768
#define HD    512

// ---------------------------------------------------------------------------
// primitives (sm_80+ path; no 'a'-suffix features)
// ---------------------------------------------------------------------------
__device__ __forceinline__ uint32_t smem_to_u32(const void* p) {
    uint32_t a;
    asm("{ .reg .u64 t; cvta.to.shared.u64 t, %1; cvt.u32.u64 %0, t; }" : "=r"(a) : "l"(p));
    return a;
}
__device__ __forceinline__ float tanh_ap(float x) {
    float y;
    asm("tanh.approx.f32 %0, %1;" : "=f"(y) : "f"(x));
    return y;
}

#define LDMATRIX_X4(r0, r1, r2, r3, addr) \
    asm volatile("ldmatrix.sync.aligned.m8n8.x4.shared.b16 {%0,%1,%2,%3}, [%4];" \
                 : "=r"(r0), "=r"(r1), "=r"(r2), "=r"(r3) : "r"(addr))
#define MMA16816(c, a, b) \
    asm volatile("mma.sync.aligned.m16n8k16.row.col.f32.f16.f16.f32 " \
                 "{%0,%1,%2,%3}, {%4,%5,%6,%7}, {%8,%9}, {%0,%1,%2,%3};" \
                 : "+f"((c)[0]), "+f"((c)[1]), "+f"((c)[2]), "+f"((c)[3]) \
                 : "r"((a)[0]), "r"((a)[1]), "r"((a)[2]), "r"((a)[3]), \
                   "r"((b)[0]), "r"((b)[1]))
#define CP_ASYNC16(dst, src) \
    asm volatile("cp.async.cg.shared.global [%0], [%1], 16;" :: "r"(dst), "l"(src))
#define CP_COMMIT() asm volatile("cp.async.commit_group;" ::: "memory")
#define CP_WAIT1()  asm volatile("cp.async.wait_group 1;" ::: "memory")

// ---------------------------------------------------------------------------
// device scratch (no allocations allowed)
// ---------------------------------------------------------------------------
__device__ int g_cnt0, g_cnt1;
__device__ int g_idx0[NROWS], g_idx1[NROWS];
__device__ __align__(16) __half g_A1L[(size_t)NROWS * 1536];  // stage-1 A, left (compact fp16)
__device__ __align__(16) __half g_A1R[(size_t)NROWS * 1536];  // stage-1 A, right
__device__ __align__(16) __half g_A2L[(size_t)NROWS * 512];   // stage-2 A, left (= hL)
__device__ __align__(16) __half g_A2R[(size_t)NROWS * 1024];  // stage-2 A, right (= [hR|lft])
__device__ __align__(16) __half g_W1t[4][512 * 1536];         // l1h,l1g,r1h,r1g  [N][K] fp16
__device__ __align__(16) __half g_W2Lt[2][512 * 512];         // l2h,l2g
__device__ __align__(16) __half g_W2Rt[2][512 * 1024];        // r2h,r2g

// ---------------------------------------------------------------------------
__global__ void reset_kernel() { g_cnt0 = 0; g_cnt1 = 0; }

__global__ void __launch_bounds__(256) classify_kernel(const int* __restrict__ group,
                                                       float* __restrict__ out,
                                                       int write_mask) {
    int row = blockIdx.x;
    int g = group[row];
    if (threadIdx.x == 0) {
        if (g == 0)      { int p = atomicAdd(&g_cnt0, 1); g_idx0[p] = row; }
        else if (g == 1) { int p = atomicAdd(&g_cnt1, 1); g_idx1[p] = row; }
        if (write_mask)
            out[(size_t)NROWS * HD + row] = (g == 2) ? 1.0f : 0.0f;
    }
    if (g == 2) {
        float2* o = (float2*)(out + (size_t)row * HD);
        for (int i = threadIdx.x; i < HD / 2; i += 256)
            o[i] = make_float2(0.0f, 0.0f);
    }
}

__device__ __forceinline__ uint4 cvt8(const float4* sp) {
    float4 f0 = sp[0], f1 = sp[1];
    __half2 h0 = __floats2half2_rn(f0.x, f0.y);
    __half2 h1 = __floats2half2_rn(f0.z, f0.w);
    __half2 h2 = __floats2half2_rn(f1.x, f1.y);
    __half2 h3 = __floats2half2_rn(f1.z, f1.w);
    uint4 v;
    v.x = *(uint32_t*)&h0; v.y = *(uint32_t*)&h1;
    v.z = *(uint32_t*)&h2; v.w = *(uint32_t*)&h3;
    return v;
}

// ---------------------------------------------------------------------------
// merged prep: gather/convert A buffers AND weight transpose in ONE launch.
//   blocks [0, 65536): gather (side = bid>>15, row = bid&32767)
//   blocks [65536, 65536+6144): wtrans (id = rem/768; n0/k0 from rem%768)
// ---------------------------------------------------------------------------
__global__ void __launch_bounds__(256) prep_kernel(
    const float* __restrict__ nh, const float* __restrict__ ncx,
    const float* __restrict__ le, const float* __restrict__ lft,
    const float* __restrict__ W0, const float* __restrict__ W1,
    const float* __restrict__ W2, const float* __restrict__ W3,
    const float* __restrict__ W4, const float* __restrict__ W5,
    const float* __restrict__ W6, const float* __restrict__ W7)
{
    __shared__ float t[32][33];
    const int bid = blockIdx.x;
    if (bid < 65536) {
        const int side = bid >> 15;
        const int i = bid & 32767;
        const int cnt = side ? g_cnt1 : g_cnt0;
        if (i >= cnt) return;
        const int gr = (side ? g_idx1 : g_idx0)[i];
        __half* dst1 = (side ? g_A1R : g_A1L) + (size_t)i * 1536;
        const int th = threadIdx.x;
        if (th < 192) {
            int kk = th * 8;
            const float* src = (kk < 512) ? nh : (kk < 1024) ? ncx : le;
            *(uint4*)(dst1 + kk) = cvt8((const float4*)(src + (size_t)gr * 512 + (kk & 511)));
        } else if (side) {
            int kk = (th - 192) * 8;  // 64 threads x 8 halfs = 512
            *(uint4*)(g_A2R + (size_t)i * 1024 + 512 + kk) =
                cvt8((const float4*)(lft + (size_t)gr * 512 + kk));
        }
        return;
    }
    // ---- weight transpose ----
    const int wb = bid - 65536;
    const int id = wb / 768;
    const int rem = wb % 768;
    const int K = (id < 4) ? 1536 : (id < 6) ? 512 : 1024;
    const int k0 = (rem / 16) * 32;
    if (k0 >= K) return;
    const int n0 = (rem % 16) * 32;
    const float* W;
    __half* Wt;
    switch (id) {
        case 0: W = W0; Wt = g_W1t[0];  break;
        case 1: W = W1; Wt = g_W1t[1];  break;
        case 2: W = W2; Wt = g_W1t[2];  break;
        case 3: W = W3; Wt = g_W1t[3];  break;
        case 4: W = W4; Wt = g_W2Lt[0]; break;
        case 5: W = W5; Wt = g_W2Lt[1]; break;
        case 6: W = W6; Wt = g_W2Rt[0]; break;
        default: W = W7; Wt = g_W2Rt[1]; break;
    }
    const int tx = threadIdx.x & 31, ty = threadIdx.x >> 5;
    #pragma unroll
    for (int i = 0; i < 32; i += 8)
        t[ty + i][tx] = W[(size_t)(k0 + ty + i) * 512 + n0 + tx];
    __syncthreads();
    #pragma unroll
    for (int i = 0; i < 32; i += 8)
        Wt[(size_t)(n0 + ty + i) * K + k0 + tx] = __float2half(t[tx][ty + i]);
}

// ---------------------------------------------------------------------------
// gated GEMM, cp.async 3-stage pipeline, BK=64, single barrier per chunk:
//   C = tanh(A@Wh + bh) * sigmoid(A@Wg + bg)
// STAGE 1: A = g_A1{L,R} (K=1536), fp16 out -> g_A2L / g_A2R[:,0:512] compact.
// STAGE 2: A = g_A2L (K=512) / g_A2R (K=1024); fp32 out scattered to d_out.
// BM=128, BN=64 per stream (h+g), BK=64. 8 warps, each 32m x 32n x 2 streams.
// ---------------------------------------------------------------------------
#define NST   3
#define BK    64
#define LDK   72                    // padded row stride in halfs (144B)
#define ST_A  (128 * LDK)           // 9216 halfs
#define ST_B  (64 * LDK)            // 4608 halfs
#define ST_TOT (ST_A + 2 * ST_B)    // 18432 halfs = 36864 B per stage
#define SMEM_BYTES (NST * ST_TOT * 2)   // 110592 B

template <int STAGE>
__global__ void __launch_bounds__(256, 2) gemm_cp(
    const float* __restrict__ bhL, const float* __restrict__ bgL,
    const float* __restrict__ bhR, const float* __restrict__ bgR,
    float* __restrict__ outp)
{
    extern __shared__ __half smem[];
    __shared__ int s_idx[128];

    const int tid  = threadIdx.x;
    const int lane = tid & 31;
    const int wid  = tid >> 5;
    const int side = blockIdx.z;

    const int cnt  = side ? g_cnt1 : g_cnt0;
    const int row0 = blockIdx.y * 128;
    if (row0 >= cnt) return;
    const int n0 = blockIdx.x * 64;

    const int K = (STAGE == 1) ? 1536 : (side ? 1024 : 512);
    const __half* __restrict__ A;
    const __half* __restrict__ Wh;
    const __half* __restrict__ Wg;
    if (STAGE == 1) {
        A  = side ? g_A1R : g_A1L;
        Wh = g_W1t[side * 2];
        Wg = g_W1t[side * 2 + 1];
    } else {
        A  = side ? g_A2R : g_A2L;
        Wh = side ? g_W2Rt[0] : g_W2Lt[0];
        Wg = side ? g_W2Rt[1] : g_W2Lt[1];
    }
    const float* __restrict__ bh = side ? bhR : bhL;
    const float* __restrict__ bg = side ? bgR : bgL;
    __half* __restrict__ hdst = side ? g_A2R : g_A2L;
    const int K2dst = side ? 1024 : 512;   // stage-1 output row stride

    if (STAGE == 2 && tid < 128) {
        int rc = row0 + tid;
        s_idx[tid] = (rc < cnt) ? (side ? g_idx1 : g_idx0)[rc] : 0;
    }

    const uint32_t sb = smem_to_u32(smem);

    // ---- cp.async issue for chunk c (BK=64: 8 x 16B lines per row) ---------
    auto issue = [&](int c) {
        const uint32_t base = (uint32_t)(c % NST) * ST_TOT;
        const int kb = c * BK;
        // A: 128 rows x 8 lines = 1024 lines; 4 per thread
        #pragma unroll
        for (int it = 0; it < 4; ++it) {
            int l = tid + it * 256;
            int r = l >> 3, q = l & 7;
            uint32_t dst = sb + 2u * (base + r * LDK + q * 8);
            CP_ASYNC16(dst, A + (size_t)(row0 + r) * K + kb + q * 8);
        }
        // Bh / Bg: 64 rows x 8 lines = 512 lines each; 2 per thread per stream
        #pragma unroll
        for (int it = 0; it < 2; ++it) {
            int l = tid + it * 256;
            int r = l >> 3, q = l & 7;
            uint32_t dh = sb + 2u * (base + ST_A + r * LDK + q * 8);
            CP_ASYNC16(dh, Wh + (size_t)(n0 + r) * K + kb + q * 8);
            CP_ASYNC16(dh + 2u * ST_B, Wg + (size_t)(n0 + r) * K + kb + q * 8);
        }
    };

    // ---- fragment addressing ------------------------------------------------
    const int wm = wid & 3;
    const int wn = wid >> 2;
    const int rowA = wm * 32 + (lane & 15);
    const int colA = (lane >> 4) * 8;
    // B via ldmatrix.x4: m0/m1 = rows n..n+7 (k lo/hi), m2/m3 = rows n+8..n+15
    const int rowB = wn * 32 + (lane & 7) + ((lane >> 4) << 3);
    const int colB = ((lane >> 3) & 1) * 8;

    float ah[2][4][4];
    float ag[2][4][4];
    #pragma unroll
    for (int i = 0; i < 2; i++)
        #pragma unroll
        for (int j = 0; j < 4; j++)
            #pragma unroll
            for (int q = 0; q < 4; q++) { ah[i][j][q] = 0.f; ag[i][j][q] = 0.f; }

    const int nch = K / BK;
    issue(0); CP_COMMIT();
    issue(1); CP_COMMIT();

    for (int c = 0; c < nch; ++c) {
        CP_WAIT1();
        __syncthreads();
        // prefetch chunk c+2: its buffer ((c-1)%3) was consumed in iter c-1,
        // and the barrier above guarantees all warps are past it.
        if (c + 2 < nch) { issue(c + 2); }
        CP_COMMIT();

        const uint32_t base = (uint32_t)(c % NST) * ST_TOT;
        #pragma unroll 2
        for (int k16 = 0; k16 < 4; ++k16) {
            const int kk = k16 * 16;
            uint32_t a[2][4];
            #pragma unroll
            for (int mt = 0; mt < 2; ++mt) {
                uint32_t ad = sb + 2u * (base + (rowA + mt * 16) * LDK + kk + colA);
                LDMATRIX_X4(a[mt][0], a[mt][1], a[mt][2], a[mt][3], ad);
            }
            uint32_t bhf[4][2], bgf[4][2];
            #pragma unroll
            for (int p = 0; p < 2; ++p) {
                uint32_t oh = sb + 2u * (base + ST_A + (rowB + p * 16) * LDK + kk + colB);
                LDMATRIX_X4(bhf[2 * p][0], bhf[2 * p][1], bhf[2 * p + 1][0], bhf[2 * p + 1][1], oh);
                LDMATRIX_X4(bgf[2 * p][0], bgf[2 * p][1], bgf[2 * p + 1][0], bgf[2 * p + 1][1],
                            oh + 2u * ST_B);
            }
            #pragma unroll
            for (int mt = 0; mt < 2; ++mt)
                #pragma unroll
                for (int nt = 0; nt < 4; ++nt) {
                    MMA16816(ah[mt][nt], a[mt], bhf[nt]);
                    MMA16816(ag[mt][nt], a[mt], bgf[nt]);
                }
        }
    }

    // ---- epilogue: bias + tanh * sigmoid ------------------------------------
    const int r0l   = wm * 32 + (lane >> 2);
    const int cbase = wn * 32 + (lane & 3) * 2;

    float bhv[4][2], bgv[4][2];
    #pragma unroll
    for (int nt = 0; nt < 4; ++nt) {
        int ncol = n0 + cbase + nt * 8;
        bhv[nt][0] = bh[ncol]; bhv[nt][1] = bh[ncol + 1];
        bgv[nt][0] = bg[ncol]; bgv[nt][1] = bg[ncol + 1];
    }

    #pragma unroll
    for (int mt = 0; mt < 2; ++mt) {
        #pragma unroll
        for (int hf = 0; hf < 2; ++hf) {
            const int rloc = r0l + mt * 16 + hf * 8;
            const int rc = row0 + rloc;
            if (rc >= cnt) continue;
            #pragma unroll
            for (int nt = 0; nt < 4; ++nt) {
                const int ncol = n0 + cbase + nt * 8;
                float hv0 = ah[mt][nt][hf * 2 + 0] + bhv[nt][0];
                float hv1 = ah[mt][nt][hf * 2 + 1] + bhv[nt][1];
                float gv0 = ag[mt][nt][hf * 2 + 0] + bgv[nt][0];
                float gv1 = ag[mt][nt][hf * 2 + 1] + bgv[nt][1];
                float o0 = tanh_ap(hv0) * (0.5f * tanh_ap(0.5f * gv0) + 0.5f);
                float o1 = tanh_ap(hv1) * (0.5f * tanh_ap(0.5f * gv1) + 0.5f);
                if (STAGE == 1) {
                    *(__half2*)&hdst[(size_t)rc * K2dst + ncol] = __floats2half2_rn(o0, o1);
                } else {
                    *(float2*)&outp[(size_t)s_idx[rloc] * 512 + ncol] = make_float2(o0, o1);
                }
            }
        }
    }
}

// ---------------------------------------------------------------------------
extern "C" void kernel_launch(void* const* d_in, const int* in_sizes, int n_in,
                              void* d_out, int out_size) {
    const float* nh   = (const float*)d_in[0];
    const float* nc   = (const float*)d_in[1];
    const float* le   = (const float*)d_in[2];
    const float* lft  = (const float*)d_in[3];
    const int*   grp  = (const int*)  d_in[4];
    const float* Wl1h = (const float*)d_in[5];
    const float* bl1h = (const float*)d_in[6];
    const float* Wl1g = (const float*)d_in[7];
    const float* bl1g = (const float*)d_in[8];
    const float* Wl2h = (const float*)d_in[9];
    const float* bl2h = (const float*)d_in[10];
    const float* Wl2g = (const float*)d_in[11];
    const float* bl2g = (const float*)d_in[12];
    const float* Wr1h = (const float*)d_in[13];
    const float* br1h = (const float*)d_in[14];
    const float* Wr1g = (const float*)d_in[15];
    const float* br1g = (const float*)d_in[16];
    const float* Wr2h = (const float*)d_in[17];
    const float* br2h = (const float*)d_in[18];
    const float* Wr2g = (const float*)d_in[19];
    const float* br2g = (const float*)d_in[20];

    float* out = (float*)d_out;
    const int write_mask = (out_size >= NROWS * HD + NROWS) ? 1 : 0;

    cudaFuncSetAttribute(gemm_cp<1>, cudaFuncAttributeMaxDynamicSharedMemorySize, SMEM_BYTES);
    cudaFuncSetAttribute(gemm_cp<2>, cudaFuncAttributeMaxDynamicSharedMemorySize, SMEM_BYTES);

    reset_kernel<<<1, 1>>>();
    classify_kernel<<<NROWS, 256>>>(grp, out, write_mask);
    prep_kernel<<<65536 + 6144, 256>>>(nh, nc, le, lft,
                                       Wl1h, Wl1g, Wr1h, Wr1g, Wl2h, Wl2g, Wr2h, Wr2g);

    dim3 grid(8, NROWS / 128, 2);
    gemm_cp<1><<<grid, 256, SMEM_BYTES>>>(bl1h, bl1g, br1h, br1g, nullptr);
    gemm_cp<2><<<grid, 256, SMEM_BYTES>>>(bl2h, bl2g, br2h, br2g, out);
}

// round 12
// speedup vs baseline: 6.3249x; 1.1486x over previous
#include <cuda_runtime.h>
#include <cuda_fp16.h>
#include <math.h>
#include <stdint.h>

#define NROWS 32768
#define HD    512

// ---------------------------------------------------------------------------
// primitives (sm_80+ path; no 'a'-suffix features)
// ---------------------------------------------------------------------------
__device__ __forceinline__ uint32_t smem_to_u32(const void* p) {
    uint32_t a;
    asm("{ .reg .u64 t; cvta.to.shared.u64 t, %1; cvt.u32.u64 %0, t; }" : "=r"(a) : "l"(p));
    return a;
}
__device__ __forceinline__ float tanh_ap(float x) {
    float y;
    asm("tanh.approx.f32 %0, %1;" : "=f"(y) : "f"(x));
    return y;
}

#define LDMATRIX_X4(r0, r1, r2, r3, addr) \
    asm volatile("ldmatrix.sync.aligned.m8n8.x4.shared.b16 {%0,%1,%2,%3}, [%4];" \
                 : "=r"(r0), "=r"(r1), "=r"(r2), "=r"(r3) : "r"(addr))
#define MMA16816(c, a, b) \
    asm volatile("mma.sync.aligned.m16n8k16.row.col.f32.f16.f16.f32 " \
                 "{%0,%1,%2,%3}, {%4,%5,%6,%7}, {%8,%9}, {%0,%1,%2,%3};" \
                 : "+f"((c)[0]), "+f"((c)[1]), "+f"((c)[2]), "+f"((c)[3]) \
                 : "r"((a)[0]), "r"((a)[1]), "r"((a)[2]), "r"((a)[3]), \
                   "r"((b)[0]), "r"((b)[1]))
#define CP_ASYNC16(dst, src) \
    asm volatile("cp.async.cg.shared.global [%0], [%1], 16;" :: "r"(dst), "l"(src))
#define CP_COMMIT() asm volatile("cp.async.commit_group;" ::: "memory")
#define CP_WAIT1()  asm volatile("cp.async.wait_group 1;" ::: "memory")

// ---------------------------------------------------------------------------
// device scratch (no allocations allowed)
// ---------------------------------------------------------------------------
__device__ int g_cnt0, g_cnt1;
__device__ int g_idx0[NROWS], g_idx1[NROWS];
__device__ __align__(16) __half g_A1L[(size_t)NROWS * 1536];  // stage-1 A, left (compact fp16)
__device__ __align__(16) __half g_A1R[(size_t)NROWS * 1536];  // stage-1 A, right
__device__ __align__(16) __half g_A2L[(size_t)NROWS * 512];   // stage-2 A, left (= hL)
__device__ __align__(16) __half g_A2R[(size_t)NROWS * 1024];  // stage-2 A, right (= [hR|lft])
__device__ __align__(16) __half g_W1t[4][512 * 1536];         // l1h,l1g,r1h,r1g  [N][K] fp16
__device__ __align__(16) __half g_W2Lt[2][512 * 512];         // l2h,l2g
__device__ __align__(16) __half g_W2Rt[2][512 * 1024];        // r2h,r2g

// ---------------------------------------------------------------------------
__global__ void reset_kernel() { g_cnt0 = 0; g_cnt1 = 0; }

// classify: 128 blocks x 256 threads, warp-aggregated atomics + coalesced zero
__global__ void __launch_bounds__(256) classify_kernel(const int* __restrict__ group,
                                                       float* __restrict__ out,
                                                       int write_mask) {
    __shared__ int s_g[256];
    const int tid = threadIdx.x;
    const int row = blockIdx.x * 256 + tid;
    const int lane = tid & 31;
    const int g = group[row];
    s_g[tid] = g;
    if (write_mask)
        out[(size_t)NROWS * HD + row] = (g == 2) ? 1.0f : 0.0f;

    // warp-aggregated compaction for g==0 and g==1
    unsigned m0 = __ballot_sync(0xFFFFFFFFu, g == 0);
    unsigned m1 = __ballot_sync(0xFFFFFFFFu, g == 1);
    int base0 = 0, base1 = 0;
    if (lane == 0) {
        if (m0) base0 = atomicAdd(&g_cnt0, __popc(m0));
        if (m1) base1 = atomicAdd(&g_cnt1, __popc(m1));
    }
    base0 = __shfl_sync(0xFFFFFFFFu, base0, 0);
    base1 = __shfl_sync(0xFFFFFFFFu, base1, 0);
    unsigned below = (1u << lane) - 1u;
    if (g == 0) g_idx0[base0 + __popc(m0 & below)] = row;
    if (g == 1) g_idx1[base1 + __popc(m1 & below)] = row;

    __syncthreads();
    // zero finished rows (coalesced: whole block per row)
    const int row_base = blockIdx.x * 256;
    for (int r = 0; r < 256; ++r) {
        if (s_g[r] == 2) {
            float2* o = (float2*)(out + (size_t)(row_base + r) * HD);
            o[tid] = make_float2(0.0f, 0.0f);   // 256 threads x 8B = 2KB = full row
        }
    }
}

__device__ __forceinline__ uint4 cvt8(const float4* sp) {
    float4 f0 = sp[0], f1 = sp[1];
    __half2 h0 = __floats2half2_rn(f0.x, f0.y);
    __half2 h1 = __floats2half2_rn(f0.z, f0.w);
    __half2 h2 = __floats2half2_rn(f1.x, f1.y);
    __half2 h3 = __floats2half2_rn(f1.z, f1.w);
    uint4 v;
    v.x = *(uint32_t*)&h0; v.y = *(uint32_t*)&h1;
    v.z = *(uint32_t*)&h2; v.w = *(uint32_t*)&h3;
    return v;
}

// ---------------------------------------------------------------------------
// merged prep: gather/convert A buffers AND weight transpose in ONE launch.
//   blocks [0, 8192): gather, 8 compact rows per block (side = bid>>12)
//   blocks [8192, 8192+6144): wtrans (id = rem/768)
// ---------------------------------------------------------------------------
__global__ void __launch_bounds__(256) prep_kernel(
    const float* __restrict__ nh, const float* __restrict__ ncx,
    const float* __restrict__ le, const float* __restrict__ lft,
    const float* __restrict__ W0, const float* __restrict__ W1,
    const float* __restrict__ W2, const float* __restrict__ W3,
    const float* __restrict__ W4, const float* __restrict__ W5,
    const float* __restrict__ W6, const float* __restrict__ W7)
{
    __shared__ float t[32][33];
    __shared__ int s_gr[8];
    const int bid = blockIdx.x;
    const int th = threadIdx.x;
    if (bid < 8192) {
        const int side = bid >> 12;
        const int i0 = (bid & 4095) * 8;
        const int cnt = side ? g_cnt1 : g_cnt0;
        if (i0 >= cnt) return;
        const int* __restrict__ idx = side ? g_idx1 : g_idx0;
        if (th < 8) s_gr[th] = (i0 + th < cnt) ? idx[i0 + th] : -1;
        __syncthreads();
        __half* dstA = (side ? g_A1R : g_A1L) + (size_t)i0 * 1536;
        // A1: 8 rows x 192 uint4 = 1536 uint4; 6 per thread
        #pragma unroll
        for (int j = 0; j < 6; ++j) {
            int l = th + j * 256;
            int r = l / 192, q = l % 192;
            int gr = s_gr[r];
            if (gr < 0) continue;
            int kk = q * 8;
            const float* src = (kk < 512) ? nh : (kk < 1024) ? ncx : le;
            *(uint4*)(dstA + (size_t)r * 1536 + kk) =
                cvt8((const float4*)(src + (size_t)gr * 512 + (kk & 511)));
        }
        // lft into g_A2R cols [512,1024): 8 rows x 64 uint4 = 512; 2 per thread
        if (side) {
            #pragma unroll
            for (int j = 0; j < 2; ++j) {
                int l = th + j * 256;
                int r = l >> 6, q = l & 63;
                int gr = s_gr[r];
                if (gr < 0) continue;
                int kk = q * 8;
                *(uint4*)(g_A2R + (size_t)(i0 + r) * 1024 + 512 + kk) =
                    cvt8((const float4*)(lft + (size_t)gr * 512 + kk));
            }
        }
        return;
    }
    // ---- weight transpose ----
    const int wb = bid - 8192;
    const int id = wb / 768;
    const int rem = wb % 768;
    const int K = (id < 4) ? 1536 : (id < 6) ? 512 : 1024;
    const int k0 = (rem / 16) * 32;
    if (k0 >= K) return;
    const int n0 = (rem % 16) * 32;
    const float* W;
    __half* Wt;
    switch (id) {
        case 0: W = W0; Wt = g_W1t[0];  break;
        case 1: W = W1; Wt = g_W1t[1];  break;
        case 2: W = W2; Wt = g_W1t[2];  break;
        case 3: W = W3; Wt = g_W1t[3];  break;
        case 4: W = W4; Wt = g_W2Lt[0]; break;
        case 5: W = W5; Wt = g_W2Lt[1]; break;
        case 6: W = W6; Wt = g_W2Rt[0]; break;
        default: W = W7; Wt = g_W2Rt[1]; break;
    }
    const int tx = th & 31, ty = th >> 5;
    #pragma unroll
    for (int i = 0; i < 32; i += 8)
        t[ty + i][tx] = W[(size_t)(k0 + ty + i) * 512 + n0 + tx];
    __syncthreads();
    #pragma unroll
    for (int i = 0; i < 32; i += 8)
        Wt[(size_t)(n0 + ty + i) * K + k0 + tx] = __float2half(t[tx][ty + i]);
}

// ---------------------------------------------------------------------------
// gated GEMM, cp.async 3-stage pipeline, BK=64, single barrier per chunk:
//   C = tanh(A@Wh + bh) * sigmoid(A@Wg + bg)
// STAGE 1: A = g_A1{L,R} (K=1536), fp16 out -> g_A2L / g_A2R[:,0:512] compact.
// STAGE 2: A = g_A2L (K=512) / g_A2R (K=1024); fp32 out scattered to d_out.
// BM=128, BN=64 per stream (h+g), BK=64. 8 warps, each 32m x 32n x 2 streams.
// ---------------------------------------------------------------------------
#define NST   3
#define BK    64
#define LDK   72                    // padded row stride in halfs (144B)
#define ST_A  (128 * LDK)           // 9216 halfs
#define ST_B  (64 * LDK)            // 4608 halfs
#define ST_TOT (ST_A + 2 * ST_B)    // 18432 halfs = 36864 B per stage
#define SMEM_BYTES (NST * ST_TOT * 2)   // 110592 B

template <int STAGE>
__global__ void __launch_bounds__(256, 2) gemm_cp(
    const float* __restrict__ bhL, const float* __restrict__ bgL,
    const float* __restrict__ bhR, const float* __restrict__ bgR,
    float* __restrict__ outp)
{
    extern __shared__ __half smem[];
    __shared__ int s_idx[128];

    const int tid  = threadIdx.x;
    const int lane = tid & 31;
    const int wid  = tid >> 5;
    const int side = blockIdx.z;

    const int cnt  = side ? g_cnt1 : g_cnt0;
    const int row0 = blockIdx.y * 128;
    if (row0 >= cnt) return;
    const int n0 = blockIdx.x * 64;

    const int K = (STAGE == 1) ? 1536 : (side ? 1024 : 512);
    const __half* __restrict__ A;
    const __half* __restrict__ Wh;
    const __half* __restrict__ Wg;
    if (STAGE == 1) {
        A  = side ? g_A1R : g_A1L;
        Wh = g_W1t[side * 2];
        Wg = g_W1t[side * 2 + 1];
    } else {
        A  = side ? g_A2R : g_A2L;
        Wh = side ? g_W2Rt[0] : g_W2Lt[0];
        Wg = side ? g_W2Rt[1] : g_W2Lt[1];
    }
    const float* __restrict__ bh = side ? bhR : bhL;
    const float* __restrict__ bg = side ? bgR : bgL;
    __half* __restrict__ hdst = side ? g_A2R : g_A2L;
    const int K2dst = side ? 1024 : 512;   // stage-1 output row stride

    if (STAGE == 2 && tid < 128) {
        int rc = row0 + tid;
        s_idx[tid] = (rc < cnt) ? (side ? g_idx1 : g_idx0)[rc] : 0;
    }

    const uint32_t sb = smem_to_u32(smem);

    // ---- cp.async issue for chunk c (BK=64: 8 x 16B lines per row) ---------
    auto issue = [&](int c) {
        const uint32_t base = (uint32_t)(c % NST) * ST_TOT;
        const int kb = c * BK;
        // A: 128 rows x 8 lines = 1024 lines; 4 per thread
        #pragma unroll
        for (int it = 0; it < 4; ++it) {
            int l = tid + it * 256;
            int r = l >> 3, q = l & 7;
            uint32_t dst = sb + 2u * (base + r * LDK + q * 8);
            CP_ASYNC16(dst, A + (size_t)(row0 + r) * K + kb + q * 8);
        }
        // Bh / Bg: 64 rows x 8 lines = 512 lines each; 2 per thread per stream
        #pragma unroll
        for (int it = 0; it < 2; ++it) {
            int l = tid + it * 256;
            int r = l >> 3, q = l & 7;
            uint32_t dh = sb + 2u * (base + ST_A + r * LDK + q * 8);
            CP_ASYNC16(dh, Wh + (size_t)(n0 + r) * K + kb + q * 8);
            CP_ASYNC16(dh + 2u * ST_B, Wg + (size_t)(n0 + r) * K + kb + q * 8);
        }
    };

    // ---- fragment addressing ------------------------------------------------
    const int wm = wid & 3;
    const int wn = wid >> 2;
    const int rowA = wm * 32 + (lane & 15);
    const int colA = (lane >> 4) * 8;
    // B via ldmatrix.x4: m0/m1 = rows n..n+7 (k lo/hi), m2/m3 = rows n+8..n+15
    const int rowB = wn * 32 + (lane & 7) + ((lane >> 4) << 3);
    const int colB = ((lane >> 3) & 1) * 8;

    float ah[2][4][4];
    float ag[2][4][4];
    #pragma unroll
    for (int i = 0; i < 2; i++)
        #pragma unroll
        for (int j = 0; j < 4; j++)
            #pragma unroll
            for (int q = 0; q < 4; q++) { ah[i][j][q] = 0.f; ag[i][j][q] = 0.f; }

    const int nch = K / BK;
    issue(0); CP_COMMIT();
    issue(1); CP_COMMIT();

    for (int c = 0; c < nch; ++c) {
        CP_WAIT1();
        __syncthreads();
        // prefetch chunk c+2: its buffer ((c-1)%3) was consumed in iter c-1,
        // and the barrier above guarantees all warps are past it.
        if (c + 2 < nch) { issue(c + 2); }
        CP_COMMIT();

        const uint32_t base = (uint32_t)(c % NST) * ST_TOT;
        #pragma unroll
        for (int k16 = 0; k16 < 4; ++k16) {
            const int kk = k16 * 16;
            uint32_t a[2][4];
            #pragma unroll
            for (int mt = 0; mt < 2; ++mt) {
                uint32_t ad = sb + 2u * (base + (rowA + mt * 16) * LDK + kk + colA);
                LDMATRIX_X4(a[mt][0], a[mt][1], a[mt][2], a[mt][3], ad);
            }
            uint32_t bhf[4][2], bgf[4][2];
            #pragma unroll
            for (int p = 0; p < 2; ++p) {
                uint32_t oh = sb + 2u * (base + ST_A + (rowB + p * 16) * LDK + kk + colB);
                LDMATRIX_X4(bhf[2 * p][0], bhf[2 * p][1], bhf[2 * p + 1][0], bhf[2 * p + 1][1], oh);
                LDMATRIX_X4(bgf[2 * p][0], bgf[2 * p][1], bgf[2 * p + 1][0], bgf[2 * p + 1][1],
                            oh + 2u * ST_B);
            }
            #pragma unroll
            for (int mt = 0; mt < 2; ++mt)
                #pragma unroll
                for (int nt = 0; nt < 4; ++nt) {
                    MMA16816(ah[mt][nt], a[mt], bhf[nt]);
                    MMA16816(ag[mt][nt], a[mt], bgf[nt]);
                }
        }
    }

    // ---- epilogue: bias + tanh * sigmoid ------------------------------------
    const int r0l   = wm * 32 + (lane >> 2);
    const int cbase = wn * 32 + (lane & 3) * 2;

    float bhv[4][2], bgv[4][2];
    #pragma unroll
    for (int nt = 0; nt < 4; ++nt) {
        int ncol = n0 + cbase + nt * 8;
        bhv[nt][0] = bh[ncol]; bhv[nt][1] = bh[ncol + 1];
        bgv[nt][0] = bg[ncol]; bgv[nt][1] = bg[ncol + 1];
    }

    #pragma unroll
    for (int mt = 0; mt < 2; ++mt) {
        #pragma unroll
        for (int hf = 0; hf < 2; ++hf) {
            const int rloc = r0l + mt * 16 + hf * 8;
            const int rc = row0 + rloc;
            if (rc >= cnt) continue;
            #pragma unroll
            for (int nt = 0; nt < 4; ++nt) {
                const int ncol = n0 + cbase + nt * 8;
                float hv0 = ah[mt][nt][hf * 2 + 0] + bhv[nt][0];
                float hv1 = ah[mt][nt][hf * 2 + 1] + bhv[nt][1];
                float gv0 = ag[mt][nt][hf * 2 + 0] + bgv[nt][0];
                float gv1 = ag[mt][nt][hf * 2 + 1] + bgv[nt][1];
                float o0 = tanh_ap(hv0) * (0.5f * tanh_ap(0.5f * gv0) + 0.5f);
                float o1 = tanh_ap(hv1) * (0.5f * tanh_ap(0.5f * gv1) + 0.5f);
                if (STAGE == 1) {
                    *(__half2*)&hdst[(size_t)rc * K2dst + ncol] = __floats2half2_rn(o0, o1);
                } else {
                    *(float2*)&outp[(size_t)s_idx[rloc] * 512 + ncol] = make_float2(o0, o1);
                }
            }
        }
    }
}

// ---------------------------------------------------------------------------
extern "C" void kernel_launch(void* const* d_in, const int* in_sizes, int n_in,
                              void* d_out, int out_size) {
    const float* nh   = (const float*)d_in[0];
    const float* nc   = (const float*)d_in[1];
    const float* le   = (const float*)d_in[2];
    const float* lft  = (const float*)d_in[3];
    const int*   grp  = (const int*)  d_in[4];
    const float* Wl1h = (const float*)d_in[5];
    const float* bl1h = (const float*)d_in[6];
    const float* Wl1g = (const float*)d_in[7];
    const float* bl1g = (const float*)d_in[8];
    const float* Wl2h = (const float*)d_in[9];
    const float* bl2h = (const float*)d_in[10];
    const float* Wl2g = (const float*)d_in[11];
    const float* bl2g = (const float*)d_in[12];
    const float* Wr1h = (const float*)d_in[13];
    const float* br1h = (const float*)d_in[14];
    const float* Wr1g = (const float*)d_in[15];
    const float* br1g = (const float*)d_in[16];
    const float* Wr2h = (const float*)d_in[17];
    const float* br2h = (const float*)d_in[18];
    const float* Wr2g = (const float*)d_in[19];
    const float* br2g = (const float*)d_in[20];

    float* out = (float*)d_out;
    const int write_mask = (out_size >= NROWS * HD + NROWS) ? 1 : 0;

    cudaFuncSetAttribute(gemm_cp<1>, cudaFuncAttributeMaxDynamicSharedMemorySize, SMEM_BYTES);
    cudaFuncSetAttribute(gemm_cp<2>, cudaFuncAttributeMaxDynamicSharedMemorySize, SMEM_BYTES);

    reset_kernel<<<1, 1>>>();
    classify_kernel<<<NROWS / 256, 256>>>(grp, out, write_mask);
    prep_kernel<<<8192 + 6144, 256>>>(nh, nc, le, lft,
                                      Wl1h, Wl1g, Wr1h, Wr1g, Wl2h, Wl2g, Wr2h, Wr2g);

    dim3 grid(8, NROWS / 128, 2);
    gemm_cp<1><<<grid, 256, SMEM_BYTES>>>(bl1h, bl1g, br1h, br1g, nullptr);
    gemm_cp<2><<<grid, 256, SMEM_BYTES>>>(bl2h, bl2g, br2h, br2g, out);
}